// round 1
// baseline (speedup 1.0000x reference)
#include <cuda_runtime.h>
#include <math.h>
#include <float.h>

// Problem constants
#define HEADS   2
#define K_DIM   16
#define HALF_D  8
#define KNN     8
#define N_KEYS  256
#define D_IN    1024
#define H_DIM   128

#define BM      32      // tokens per block
#define BK      32      // K-tile for GEMM1
#define NTHREADS 256

// W1 transposed scratch: W1T[k][c] = W1[c][k], 1024 x 128
__device__ float g_W1T[D_IN * H_DIM];

// ---------------------------------------------------------------------------
// Kernel 0: transpose W1 (128 x 1024, row-major) -> g_W1T (1024 x 128)
// ---------------------------------------------------------------------------
__global__ void transpose_w1_kernel(const float* __restrict__ W1) {
    __shared__ float tile[32][33];
    const int bx = blockIdx.x;   // k-tile: 0..31
    const int by = blockIdx.y;   // c-tile: 0..3
    const int tx = threadIdx.x;  // 0..31
    const int ty = threadIdx.y;  // 0..7
#pragma unroll
    for (int i = 0; i < 32; i += 8) {
        tile[ty + i][tx] = W1[(size_t)(by * 32 + ty + i) * D_IN + bx * 32 + tx];
    }
    __syncthreads();
#pragma unroll
    for (int i = 0; i < 32; i += 8) {
        g_W1T[(size_t)(bx * 32 + ty + i) * H_DIM + by * 32 + tx] = tile[tx][ty + i];
    }
}

// ---------------------------------------------------------------------------
// Shared memory layout (all field offsets 16B-aligned)
// ---------------------------------------------------------------------------
struct SmemLayout {
    float xs[BK * 36];          // x tile, k-major, padded stride 36 (16B-aligned rows)
    float w1s[BK * H_DIM];      // W1T tile, k-major
    float hs[BM * 132];         // h = relu(x W1^T + b1), padded stride 132
    float w2s[32 * 132];        // W2 rows, padded stride 132
    float qs[BM * 32];          // q[t][h*16+c]
    float keysb[1024 * 9];      // keys[h][half][n][c], rows padded to 9
    float ws[BM * 16];          // softmax weights per token (h-major)
    int   idxs[BM * 16];        // value row indices per token
    float top_s[8 * 2 * 8];     // per-warp: top-8 scores for each half
    int   top_i[8 * 2 * 8];     // per-warp: top-8 indices for each half
    float b1s[H_DIM];
    float b2s[32];
};

// Monotonic float <-> uint mapping (preserves total order incl. negatives)
__device__ __forceinline__ unsigned fmap(float f) {
    unsigned u = __float_as_uint(f);
    return (u & 0x80000000u) ? ~u : (u | 0x80000000u);
}
__device__ __forceinline__ float funmap(unsigned m) {
    return (m & 0x80000000u) ? __uint_as_float(m & 0x7FFFFFFFu)
                             : __uint_as_float(~m);
}

// Warp-collective exact top-8 of 256 values (lane owns n = lane + 32*j, j<8).
// Writes descending scores + indices to smem (lane 0). Ties -> lowest n.
__device__ __forceinline__ void topk8_256(float sv[8], int lane,
                                          float* top_s, int* top_i) {
    for (int k = 0; k < KNN; k++) {
        float best = sv[0];
        int bj = 0;
#pragma unroll
        for (int j = 1; j < 8; j++) {
            if (sv[j] > best) { best = sv[j]; bj = j; }
        }
        unsigned u = fmap(best);
        unsigned g = __reduce_max_sync(0xFFFFFFFFu, u);
        unsigned cand = (u == g) ? (unsigned)(lane + 32 * bj) : 0xFFFFFFFFu;
        unsigned nw = __reduce_min_sync(0xFFFFFFFFu, cand);
        if (lane == (int)(nw & 31u)) {
            int jw = (int)(nw >> 5);
#pragma unroll
            for (int j = 0; j < 8; j++) {
                if (j == jw) sv[j] = -FLT_MAX;
            }
        }
        if (lane == 0) { top_s[k] = funmap(g); top_i[k] = (int)nw; }
    }
}

// ---------------------------------------------------------------------------
// Main fused kernel: GEMM1+relu -> GEMM2 -> scores -> top-k -> softmax -> gather
// ---------------------------------------------------------------------------
__global__ __launch_bounds__(NTHREADS, 2)
void memlayer_kernel(const float* __restrict__ x,
                     const float* __restrict__ b1,
                     const float* __restrict__ W2,
                     const float* __restrict__ b2,
                     const float* __restrict__ keys,
                     const float* __restrict__ values,
                     float* __restrict__ out)
{
    extern __shared__ char raw_smem[];
    SmemLayout* s = reinterpret_cast<SmemLayout*>(raw_smem);

    const int tid  = threadIdx.x;
    const int lane = tid & 31;
    const int warp = tid >> 5;
    const int t0   = blockIdx.x * BM;

    // ---- preload small tensors into smem ----
    if (tid < H_DIM) s->b1s[tid] = b1[tid];
    if (tid < 32)    s->b2s[tid] = b2[tid];
    for (int e = tid; e < 32 * H_DIM; e += NTHREADS) {
        s->w2s[(e >> 7) * 132 + (e & 127)] = W2[e];
    }
    for (int e = tid; e < HEADS * 2 * N_KEYS * HALF_D; e += NTHREADS) {
        s->keysb[(e >> 3) * 9 + (e & 7)] = keys[e];
    }

    // ---- Phase 1: GEMM1  h = relu(x @ W1^T + b1), [32 x 128] ----
    const int tx = tid & 31;    // output col group (col = tx*4)
    const int ty = tid >> 5;    // output row group (tok = ty*4)
    float acc[4][4];
#pragma unroll
    for (int i = 0; i < 4; i++)
#pragma unroll
        for (int j = 0; j < 4; j++) acc[i][j] = 0.0f;

    const int ldtok = tid >> 3;  // 0..31
    const int ldkg  = tid & 7;   // 0..7
    const float* xrow = x + (size_t)(t0 + ldtok) * D_IN + ldkg * 4;

    for (int kc = 0; kc < D_IN; kc += BK) {
        float4 xv = *reinterpret_cast<const float4*>(xrow + kc);
        float4 wv[4];
#pragma unroll
        for (int r = 0; r < 4; r++) {
            int kk = warp + 8 * r;
            wv[r] = *reinterpret_cast<const float4*>(
                &g_W1T[(size_t)(kc + kk) * H_DIM + tx * 4]);
        }
        __syncthreads();  // previous tile fully consumed
        s->xs[(ldkg * 4 + 0) * 36 + ldtok] = xv.x;
        s->xs[(ldkg * 4 + 1) * 36 + ldtok] = xv.y;
        s->xs[(ldkg * 4 + 2) * 36 + ldtok] = xv.z;
        s->xs[(ldkg * 4 + 3) * 36 + ldtok] = xv.w;
#pragma unroll
        for (int r = 0; r < 4; r++) {
            int kk = warp + 8 * r;
            *reinterpret_cast<float4*>(&s->w1s[kk * H_DIM + tx * 4]) = wv[r];
        }
        __syncthreads();
#pragma unroll
        for (int kk = 0; kk < BK; kk++) {
            float4 a4 = *reinterpret_cast<const float4*>(&s->xs[kk * 36 + ty * 4]);
            float4 b4 = *reinterpret_cast<const float4*>(&s->w1s[kk * H_DIM + tx * 4]);
            float av[4] = {a4.x, a4.y, a4.z, a4.w};
            float bv[4] = {b4.x, b4.y, b4.z, b4.w};
#pragma unroll
            for (int i = 0; i < 4; i++)
#pragma unroll
                for (int j = 0; j < 4; j++) acc[i][j] += av[i] * bv[j];
        }
    }
    __syncthreads();
    {
        float4 b1v = *reinterpret_cast<const float4*>(&s->b1s[tx * 4]);
        float b1r[4] = {b1v.x, b1v.y, b1v.z, b1v.w};
#pragma unroll
        for (int i = 0; i < 4; i++) {
            float4 hv;
            hv.x = fmaxf(acc[i][0] + b1r[0], 0.0f);
            hv.y = fmaxf(acc[i][1] + b1r[1], 0.0f);
            hv.z = fmaxf(acc[i][2] + b1r[2], 0.0f);
            hv.w = fmaxf(acc[i][3] + b1r[3], 0.0f);
            *reinterpret_cast<float4*>(&s->hs[(ty * 4 + i) * 132 + tx * 4]) = hv;
        }
    }
    __syncthreads();

    // ---- Phase 2: per-(token,head) tasks: q, scores, top-k, softmax ----
    // 64 tasks (32 tokens x 2 heads), 8 warps, 8 tasks each.
    for (int it = 0; it < 8; it++) {
        const int task = it * 8 + warp;
        const int t = task >> 1;
        const int h = task & 1;

        // q[t][h*16 + l] = h_row . W2_row + b2   (lanes 0..15)
        if (lane < 16) {
            float qv = s->b2s[h * 16 + lane];
            const float* hrow = &s->hs[t * 132];
            const float* wrow = &s->w2s[(h * 16 + lane) * 132];
#pragma unroll 8
            for (int i = 0; i < H_DIM; i++) qv += hrow[i] * wrow[i];
            s->qs[t * 32 + h * 16 + lane] = qv;
        }
        __syncwarp();

        float q1r[8], q2r[8];
#pragma unroll
        for (int c = 0; c < 8; c++) {
            q1r[c] = s->qs[t * 32 + h * 16 + c];
            q2r[c] = s->qs[t * 32 + h * 16 + 8 + c];
        }

        // scores: lane owns keys n = lane + 32*j
        float s1v[8], s2v[8];
        const float* k1 = &s->keysb[(h * 2 + 0) * N_KEYS * 9];
        const float* k2 = &s->keysb[(h * 2 + 1) * N_KEYS * 9];
#pragma unroll
        for (int j = 0; j < 8; j++) {
            const int n = lane + 32 * j;
            const float* kr1 = k1 + n * 9;
            const float* kr2 = k2 + n * 9;
            float a1 = 0.0f, a2 = 0.0f;
#pragma unroll
            for (int c = 0; c < 8; c++) {
                a1 += q1r[c] * kr1[c];
                a2 += q2r[c] * kr2[c];
            }
            s1v[j] = a1;
            s2v[j] = a2;
        }

        float* ts1 = &s->top_s[(warp * 2 + 0) * 8];
        float* ts2 = &s->top_s[(warp * 2 + 1) * 8];
        int*   ti1 = &s->top_i[(warp * 2 + 0) * 8];
        int*   ti2 = &s->top_i[(warp * 2 + 1) * 8];
        topk8_256(s1v, lane, ts1, ti1);
        topk8_256(s2v, lane, ts2, ti2);
        __syncwarp();

        // combined top-8 of 64 sums; lane owns combos j2 = 2*lane, 2*lane+1
        const int a  = lane >> 2;          // == (2*lane)>>3 == (2*lane+1)>>3
        const int b0 = (2 * lane) & 7;
        float cv0 = ts1[a] + ts2[b0];
        float cv1 = ts1[a] + ts2[b0 + 1];

        float v0 = 0.0f, esum = 0.0f;
        for (int k = 0; k < KNN; k++) {
            float best;
            int slot;
            if (cv1 > cv0) { best = cv1; slot = 1; }
            else           { best = cv0; slot = 0; }
            unsigned u = fmap(best);
            unsigned g = __reduce_max_sync(0xFFFFFFFFu, u);
            unsigned cand = (u == g) ? (unsigned)(2 * lane + slot) : 0xFFFFFFFFu;
            unsigned jw = __reduce_min_sync(0xFFFFFFFFu, cand);
            float val = funmap(g);
            if (k == 0) v0 = val;
            float e = expf(val - v0);
            esum += e;
            if (lane == (int)(jw >> 1)) {
                if (jw & 1u) cv1 = -FLT_MAX;
                else         cv0 = -FLT_MAX;
            }
            if (lane == 0) {
                int aa = (int)(jw >> 3);
                int bb = (int)(jw & 7u);
                s->ws[t * 16 + h * 8 + k]   = e;                       // unnormalized
                s->idxs[t * 16 + h * 8 + k] = ti1[aa] * N_KEYS + ti2[bb];
            }
        }
        __syncwarp();
        if (lane < 8) {
            s->ws[t * 16 + h * 8 + lane] = s->ws[t * 16 + h * 8 + lane] / esum;
        }
        __syncwarp();
    }
    __syncthreads();

    // ---- Phase 3: gather  out[t] = sum_{hk} w * values[idx] ----
    const size_t c4 = (size_t)tid * 4;  // 256 threads * 4 floats = 1024 cols
    for (int t = 0; t < BM; t++) {
        float4 accv = make_float4(0.0f, 0.0f, 0.0f, 0.0f);
#pragma unroll
        for (int k = 0; k < 16; k++) {
            const float wk = s->ws[t * 16 + k];
            const int row  = s->idxs[t * 16 + k];
            const float4 v = *reinterpret_cast<const float4*>(
                &values[((size_t)row << 10) + c4]);
            accv.x += wk * v.x;
            accv.y += wk * v.y;
            accv.z += wk * v.z;
            accv.w += wk * v.w;
        }
        *reinterpret_cast<float4*>(&out[((size_t)(t0 + t) << 10) + c4]) = accv;
    }
}

// ---------------------------------------------------------------------------
// Launch
// ---------------------------------------------------------------------------
extern "C" void kernel_launch(void* const* d_in, const int* in_sizes, int n_in,
                              void* d_out, int out_size) {
    const float* x      = (const float*)d_in[0];
    const float* W1     = (const float*)d_in[1];
    const float* b1     = (const float*)d_in[2];
    const float* W2     = (const float*)d_in[3];
    const float* b2     = (const float*)d_in[4];
    const float* keys   = (const float*)d_in[5];
    const float* values = (const float*)d_in[6];
    float* out = (float*)d_out;

    const int T = in_sizes[0] / D_IN;      // 8192
    const int grid = T / BM;               // 256

    cudaFuncSetAttribute(memlayer_kernel,
                         cudaFuncAttributeMaxDynamicSharedMemorySize,
                         (int)sizeof(SmemLayout));

    transpose_w1_kernel<<<dim3(D_IN / 32, H_DIM / 32), dim3(32, 8)>>>(W1);
    memlayer_kernel<<<grid, NTHREADS, sizeof(SmemLayout)>>>(
        x, b1, W2, b2, keys, values, out);
}

// round 2
// speedup vs baseline: 1.0123x; 1.0123x over previous
#include <cuda_runtime.h>
#include <math.h>
#include <float.h>

// Problem constants
#define HEADS   2
#define K_DIM   16
#define HALF_D  8
#define KNN     8
#define N_KEYS  256
#define D_IN    1024
#define H_DIM   128

#define BM      32      // tokens per block
#define BK      32      // K-tile for GEMM1
#define NTHREADS 256

// W1 transposed scratch: W1T[k][c] = W1[c][k], 1024 x 128
__device__ float g_W1T[D_IN * H_DIM];

// ---------------------------------------------------------------------------
// Kernel 0: transpose W1 (128 x 1024, row-major) -> g_W1T (1024 x 128)
// ---------------------------------------------------------------------------
__global__ void transpose_w1_kernel(const float* __restrict__ W1) {
    __shared__ float tile[32][33];
    const int bx = blockIdx.x;   // k-tile: 0..31
    const int by = blockIdx.y;   // c-tile: 0..3
    const int tx = threadIdx.x;  // 0..31
    const int ty = threadIdx.y;  // 0..7
#pragma unroll
    for (int i = 0; i < 32; i += 8) {
        tile[ty + i][tx] = W1[(size_t)(by * 32 + ty + i) * D_IN + bx * 32 + tx];
    }
    __syncthreads();
#pragma unroll
    for (int i = 0; i < 32; i += 8) {
        g_W1T[(size_t)(bx * 32 + ty + i) * H_DIM + by * 32 + tx] = tile[tx][ty + i];
    }
}

// ---------------------------------------------------------------------------
// Shared memory layout (all field offsets 16B-aligned)
// ---------------------------------------------------------------------------
struct SmemLayout {
    float xs[BK * 36];          // x tile, k-major, padded stride 36 (16B-aligned rows)
    float w1s[BK * H_DIM];      // W1T tile, k-major
    float hs[BM * 132];         // h = relu(x W1^T + b1), padded stride 132
    float w2s[32 * 132];        // W2 rows, padded stride 132
    float qs[BM * 32];          // q[t][h*16+c]
    float keysb[1024 * 9];      // keys[h][half][n][c], rows padded to 9
    float ws[BM * 16];          // softmax weights per token (h-major)
    int   idxs[BM * 16];        // value row indices per token
    float top_s[8 * 2 * 8];     // per-warp: top-8 scores for each half
    int   top_i[8 * 2 * 8];     // per-warp: top-8 indices for each half
    float b1s[H_DIM];
    float b2s[32];
};

// Monotonic float <-> uint mapping (preserves total order incl. negatives)
__device__ __forceinline__ unsigned fmap(float f) {
    unsigned u = __float_as_uint(f);
    return (u & 0x80000000u) ? ~u : (u | 0x80000000u);
}
__device__ __forceinline__ float funmap(unsigned m) {
    return (m & 0x80000000u) ? __uint_as_float(m & 0x7FFFFFFFu)
                             : __uint_as_float(~m);
}

// Warp-collective exact top-8 of 256 values (lane owns n = lane + 32*j, j<8).
// Writes descending scores + indices to smem (lane 0). Ties -> lowest n.
__device__ __forceinline__ void topk8_256(float sv[8], int lane,
                                          float* top_s, int* top_i) {
    for (int k = 0; k < KNN; k++) {
        float best = sv[0];
        int bj = 0;
#pragma unroll
        for (int j = 1; j < 8; j++) {
            if (sv[j] > best) { best = sv[j]; bj = j; }
        }
        unsigned u = fmap(best);
        unsigned g = __reduce_max_sync(0xFFFFFFFFu, u);
        unsigned cand = (u == g) ? (unsigned)(lane + 32 * bj) : 0xFFFFFFFFu;
        unsigned nw = __reduce_min_sync(0xFFFFFFFFu, cand);
        if (lane == (int)(nw & 31u)) {
            int jw = (int)(nw >> 5);
#pragma unroll
            for (int j = 0; j < 8; j++) {
                if (j == jw) sv[j] = -FLT_MAX;
            }
        }
        if (lane == 0) { top_s[k] = funmap(g); top_i[k] = (int)nw; }
    }
}

// ---------------------------------------------------------------------------
// Main fused kernel: GEMM1+relu -> GEMM2 -> scores -> top-k -> softmax -> gather
// ---------------------------------------------------------------------------
__global__ __launch_bounds__(NTHREADS, 2)
void memlayer_kernel(const float* __restrict__ x,
                     const float* __restrict__ b1,
                     const float* __restrict__ W2,
                     const float* __restrict__ b2,
                     const float* __restrict__ keys,
                     const float* __restrict__ values,
                     float* __restrict__ out)
{
    extern __shared__ char raw_smem[];
    SmemLayout* s = reinterpret_cast<SmemLayout*>(raw_smem);

    const int tid  = threadIdx.x;
    const int lane = tid & 31;
    const int warp = tid >> 5;
    const int t0   = blockIdx.x * BM;

    // ---- preload small tensors into smem ----
    if (tid < H_DIM) s->b1s[tid] = b1[tid];
    if (tid < 32)    s->b2s[tid] = b2[tid];
    for (int e = tid; e < 32 * H_DIM; e += NTHREADS) {
        s->w2s[(e >> 7) * 132 + (e & 127)] = W2[e];
    }
    for (int e = tid; e < HEADS * 2 * N_KEYS * HALF_D; e += NTHREADS) {
        s->keysb[(e >> 3) * 9 + (e & 7)] = keys[e];
    }

    // ---- Phase 1: GEMM1  h = relu(x @ W1^T + b1), [32 x 128] ----
    const int tx = tid & 31;    // output col group (col = tx*4)
    const int ty = tid >> 5;    // output row group (tok = ty*4)
    float acc[4][4];
#pragma unroll
    for (int i = 0; i < 4; i++)
#pragma unroll
        for (int j = 0; j < 4; j++) acc[i][j] = 0.0f;

    const int ldtok = tid >> 3;  // 0..31
    const int ldkg  = tid & 7;   // 0..7
    const float* xrow = x + (size_t)(t0 + ldtok) * D_IN + ldkg * 4;

    for (int kc = 0; kc < D_IN; kc += BK) {
        float4 xv = *reinterpret_cast<const float4*>(xrow + kc);
        float4 wv[4];
#pragma unroll
        for (int r = 0; r < 4; r++) {
            int kk = warp + 8 * r;
            wv[r] = *reinterpret_cast<const float4*>(
                &g_W1T[(size_t)(kc + kk) * H_DIM + tx * 4]);
        }
        __syncthreads();  // previous tile fully consumed
        s->xs[(ldkg * 4 + 0) * 36 + ldtok] = xv.x;
        s->xs[(ldkg * 4 + 1) * 36 + ldtok] = xv.y;
        s->xs[(ldkg * 4 + 2) * 36 + ldtok] = xv.z;
        s->xs[(ldkg * 4 + 3) * 36 + ldtok] = xv.w;
#pragma unroll
        for (int r = 0; r < 4; r++) {
            int kk = warp + 8 * r;
            *reinterpret_cast<float4*>(&s->w1s[kk * H_DIM + tx * 4]) = wv[r];
        }
        __syncthreads();
#pragma unroll
        for (int kk = 0; kk < BK; kk++) {
            float4 a4 = *reinterpret_cast<const float4*>(&s->xs[kk * 36 + ty * 4]);
            float4 b4 = *reinterpret_cast<const float4*>(&s->w1s[kk * H_DIM + tx * 4]);
            float av[4] = {a4.x, a4.y, a4.z, a4.w};
            float bv[4] = {b4.x, b4.y, b4.z, b4.w};
#pragma unroll
            for (int i = 0; i < 4; i++)
#pragma unroll
                for (int j = 0; j < 4; j++) acc[i][j] += av[i] * bv[j];
        }
    }
    __syncthreads();
    {
        float4 b1v = *reinterpret_cast<const float4*>(&s->b1s[tx * 4]);
        float b1r[4] = {b1v.x, b1v.y, b1v.z, b1v.w};
#pragma unroll
        for (int i = 0; i < 4; i++) {
            float4 hv;
            hv.x = fmaxf(acc[i][0] + b1r[0], 0.0f);
            hv.y = fmaxf(acc[i][1] + b1r[1], 0.0f);
            hv.z = fmaxf(acc[i][2] + b1r[2], 0.0f);
            hv.w = fmaxf(acc[i][3] + b1r[3], 0.0f);
            *reinterpret_cast<float4*>(&s->hs[(ty * 4 + i) * 132 + tx * 4]) = hv;
        }
    }
    __syncthreads();

    // ---- Phase 2: per-(token,head) tasks: q, scores, top-k, softmax ----
    // 64 tasks (32 tokens x 2 heads), 8 warps, 8 tasks each.
    for (int it = 0; it < 8; it++) {
        const int task = it * 8 + warp;
        const int t = task >> 1;
        const int h = task & 1;

        // q[t][h*16 + l] = h_row . W2_row + b2   (lanes 0..15)
        if (lane < 16) {
            float qv = s->b2s[h * 16 + lane];
            const float* hrow = &s->hs[t * 132];
            const float* wrow = &s->w2s[(h * 16 + lane) * 132];
#pragma unroll 8
            for (int i = 0; i < H_DIM; i++) qv += hrow[i] * wrow[i];
            s->qs[t * 32 + h * 16 + lane] = qv;
        }
        __syncwarp();

        float q1r[8], q2r[8];
#pragma unroll
        for (int c = 0; c < 8; c++) {
            q1r[c] = s->qs[t * 32 + h * 16 + c];
            q2r[c] = s->qs[t * 32 + h * 16 + 8 + c];
        }

        // scores: lane owns keys n = lane + 32*j
        float s1v[8], s2v[8];
        const float* k1 = &s->keysb[(h * 2 + 0) * N_KEYS * 9];
        const float* k2 = &s->keysb[(h * 2 + 1) * N_KEYS * 9];
#pragma unroll
        for (int j = 0; j < 8; j++) {
            const int n = lane + 32 * j;
            const float* kr1 = k1 + n * 9;
            const float* kr2 = k2 + n * 9;
            float a1 = 0.0f, a2 = 0.0f;
#pragma unroll
            for (int c = 0; c < 8; c++) {
                a1 += q1r[c] * kr1[c];
                a2 += q2r[c] * kr2[c];
            }
            s1v[j] = a1;
            s2v[j] = a2;
        }

        float* ts1 = &s->top_s[(warp * 2 + 0) * 8];
        float* ts2 = &s->top_s[(warp * 2 + 1) * 8];
        int*   ti1 = &s->top_i[(warp * 2 + 0) * 8];
        int*   ti2 = &s->top_i[(warp * 2 + 1) * 8];
        topk8_256(s1v, lane, ts1, ti1);
        topk8_256(s2v, lane, ts2, ti2);
        __syncwarp();

        // combined top-8 of 64 sums; lane owns combos j2 = 2*lane, 2*lane+1
        const int a  = lane >> 2;          // == (2*lane)>>3 == (2*lane+1)>>3
        const int b0 = (2 * lane) & 7;
        float cv0 = ts1[a] + ts2[b0];
        float cv1 = ts1[a] + ts2[b0 + 1];

        float v0 = 0.0f, esum = 0.0f;
        for (int k = 0; k < KNN; k++) {
            float best;
            int slot;
            if (cv1 > cv0) { best = cv1; slot = 1; }
            else           { best = cv0; slot = 0; }
            unsigned u = fmap(best);
            unsigned g = __reduce_max_sync(0xFFFFFFFFu, u);
            unsigned cand = (u == g) ? (unsigned)(2 * lane + slot) : 0xFFFFFFFFu;
            unsigned jw = __reduce_min_sync(0xFFFFFFFFu, cand);
            float val = funmap(g);
            if (k == 0) v0 = val;
            float e = expf(val - v0);
            esum += e;
            if (lane == (int)(jw >> 1)) {
                if (jw & 1u) cv1 = -FLT_MAX;
                else         cv0 = -FLT_MAX;
            }
            if (lane == 0) {
                int aa = (int)(jw >> 3);
                int bb = (int)(jw & 7u);
                s->ws[t * 16 + h * 8 + k]   = e;                       // unnormalized
                s->idxs[t * 16 + h * 8 + k] = ti1[aa] * N_KEYS + ti2[bb];
            }
        }
        __syncwarp();
        if (lane < 8) {
            s->ws[t * 16 + h * 8 + lane] = s->ws[t * 16 + h * 8 + lane] / esum;
        }
        __syncwarp();
    }
    __syncthreads();

    // ---- Phase 3: gather  out[t] = sum_{hk} w * values[idx] ----
    const size_t c4 = (size_t)tid * 4;  // 256 threads * 4 floats = 1024 cols
    for (int t = 0; t < BM; t++) {
        float4 accv = make_float4(0.0f, 0.0f, 0.0f, 0.0f);
#pragma unroll
        for (int k = 0; k < 16; k++) {
            const float wk = s->ws[t * 16 + k];
            const int row  = s->idxs[t * 16 + k];
            const float4 v = *reinterpret_cast<const float4*>(
                &values[((size_t)row << 10) + c4]);
            accv.x += wk * v.x;
            accv.y += wk * v.y;
            accv.z += wk * v.z;
            accv.w += wk * v.w;
        }
        *reinterpret_cast<float4*>(&out[((size_t)(t0 + t) << 10) + c4]) = accv;
    }
}

// ---------------------------------------------------------------------------
// Launch
// ---------------------------------------------------------------------------
extern "C" void kernel_launch(void* const* d_in, const int* in_sizes, int n_in,
                              void* d_out, int out_size) {
    const float* x      = (const float*)d_in[0];
    const float* W1     = (const float*)d_in[1];
    const float* b1     = (const float*)d_in[2];
    const float* W2     = (const float*)d_in[3];
    const float* b2     = (const float*)d_in[4];
    const float* keys   = (const float*)d_in[5];
    const float* values = (const float*)d_in[6];
    float* out = (float*)d_out;

    const int T = in_sizes[0] / D_IN;      // 8192
    const int grid = T / BM;               // 256

    cudaFuncSetAttribute(memlayer_kernel,
                         cudaFuncAttributeMaxDynamicSharedMemorySize,
                         (int)sizeof(SmemLayout));

    transpose_w1_kernel<<<dim3(D_IN / 32, H_DIM / 32), dim3(32, 8)>>>(W1);
    memlayer_kernel<<<grid, NTHREADS, sizeof(SmemLayout)>>>(
        x, b1, W2, b2, keys, values, out);
}

// round 5
// speedup vs baseline: 1.4611x; 1.4434x over previous
#include <cuda_runtime.h>
#include <cuda_bf16.h>
#include <math.h>
#include <float.h>
#include <stdint.h>

// Problem constants
#define HEADS   2
#define K_DIM   16
#define HALF_D  8
#define KNN     8
#define N_KEYS  256
#define D_IN    1024
#define H_DIM   128

// Global scratch
__device__ float g_q[8192 * 32];                         // q: [T][32]
__device__ __nv_bfloat16 g_W1s[3 * H_DIM * D_IN];        // W1 3-way bf16 split

// ---------------------------------------------------------------------------
// 3-way bf16 split of fp32 (sum of 3 bf16 ~= fp32)
// ---------------------------------------------------------------------------
__device__ __forceinline__ void split3(float a, uint16_t& u0, uint16_t& u1,
                                       uint16_t& u2) {
    __nv_bfloat16 h0 = __float2bfloat16(a);
    float r1 = a - __bfloat162float(h0);
    __nv_bfloat16 h1 = __float2bfloat16(r1);
    float r2 = r1 - __bfloat162float(h1);
    __nv_bfloat16 h2 = __float2bfloat16(r2);
    u0 = __bfloat16_as_ushort(h0);
    u1 = __bfloat16_as_ushort(h1);
    u2 = __bfloat16_as_ushort(h2);
}
__device__ __forceinline__ uint32_t pack2(uint16_t lo, uint16_t hi) {
    return (uint32_t)lo | ((uint32_t)hi << 16);
}

__device__ __forceinline__ void mma_bf16(float* c, const uint32_t* a,
                                         const uint32_t* b) {
    asm volatile(
        "mma.sync.aligned.m16n8k16.row.col.f32.bf16.bf16.f32 "
        "{%0,%1,%2,%3}, {%4,%5,%6,%7}, {%8,%9}, {%0,%1,%2,%3};"
        : "+f"(c[0]), "+f"(c[1]), "+f"(c[2]), "+f"(c[3])
        : "r"(a[0]), "r"(a[1]), "r"(a[2]), "r"(a[3]), "r"(b[0]), "r"(b[1]));
}

// ---------------------------------------------------------------------------
// Kernel 0: pre-split W1 [128][1024] f32 -> g_W1s[3][128][1024] bf16
// ---------------------------------------------------------------------------
__global__ void split_w1_kernel(const float* __restrict__ W1) {
    int idx4 = blockIdx.x * 256 + threadIdx.x;    // over 32768 float4
    float4 v = ((const float4*)W1)[idx4];
    uint16_t a0, a1, a2, b0, b1, b2, c0, c1, c2, d0, d1, d2;
    split3(v.x, a0, a1, a2);
    split3(v.y, b0, b1, b2);
    split3(v.z, c0, c1, c2);
    split3(v.w, d0, d1, d2);
    uint2* o = (uint2*)g_W1s;
    o[0 * 32768 + idx4] = make_uint2(pack2(a0, b0), pack2(c0, d0));
    o[1 * 32768 + idx4] = make_uint2(pack2(a1, b1), pack2(c1, d1));
    o[2 * 32768 + idx4] = make_uint2(pack2(a2, b2), pack2(c2, d2));
}

// ---------------------------------------------------------------------------
// GEMM kernel: q = relu(x @ W1^T + b1) @ W2^T + b2  via mma.sync (3x-bf16)
// CTA = 64 tokens, 256 threads (8 warps: 2m x 4n), BK = 32.
//
// Accuracy note: tensor-core fp32 accumulate is round-toward-zero; chaining
// the dominant term across all of K builds a systematic ~1e-5 bias. So the
// main (A0*B0) term uses a zero-init C per 32-wide K-chunk, drained into a
// persistent fp32 accumulator with RN adds. Small correction terms (<=2^-9)
// chain freely — their RZ bias is negligible.
//
// smem byte map:
//   [0, 512)        b1s (128 f32)
//   [512, 640)      b2s (32 f32)
//   [1024, 16384)   As[3][64][40] bf16   (row stride 80B)
//   [16384, 47104)  Bs[3][128][40] bf16
//   -- union after GEMM1 --
//   [1024, 53248)   A2[3][64][136] bf16  (row stride 272B)
//   [53248, 79360)  W2s[3][32][136] bf16
// ---------------------------------------------------------------------------
#define SM_AS    1024
#define ASPL     5120      // 64*80
#define SM_BS    16384
#define BSPL     10240     // 128*80
#define SM_A2    1024
#define A2SPL    17408     // 64*272
#define SM_W2    53248
#define W2SPL    8704      // 32*272
#define SMEM_GEMM_BYTES 79360

__global__ __launch_bounds__(256, 1)
void gemm_kernel(const float* __restrict__ x, const float* __restrict__ b1,
                 const float* __restrict__ W2, const float* __restrict__ b2)
{
    extern __shared__ char sm[];
    float* b1s = (float*)(sm);
    float* b2s = (float*)(sm + 512);

    const int tid  = threadIdx.x;
    const int lane = tid & 31;
    const int warp = tid >> 5;
    const int g    = lane >> 2;      // fragment group row
    const int tig  = lane & 3;       // thread-in-group
    const int wm   = warp >> 2;      // 0..1 (m)
    const int wn   = warp & 3;       // 0..3 (n)
    const int t0   = blockIdx.x * 64;

    if (tid < 128) b1s[tid] = b1[tid];
    if (tid < 32)  b2s[tid] = b2[tid];

    // ---- W2 [32][128] -> split tiles W2s[3][32][136] ----
#pragma unroll
    for (int i = 0; i < 4; i++) {
        int idx4 = tid + i * 256;          // 1024 float4
        int n  = idx4 >> 5;
        int c4 = idx4 & 31;
        float4 v = *(const float4*)(W2 + n * H_DIM + c4 * 4);
        uint16_t a0, a1, a2, e0, e1, e2, c0, c1, c2, d0, d1, d2;
        split3(v.x, a0, a1, a2);
        split3(v.y, e0, e1, e2);
        split3(v.z, c0, c1, c2);
        split3(v.w, d0, d1, d2);
        char* base = sm + SM_W2 + n * 272 + c4 * 8;
        *(uint2*)(base + 0 * W2SPL) = make_uint2(pack2(a0, e0), pack2(c0, d0));
        *(uint2*)(base + 1 * W2SPL) = make_uint2(pack2(a1, e1), pack2(c1, d1));
        *(uint2*)(base + 2 * W2SPL) = make_uint2(pack2(a2, e2), pack2(c2, d2));
    }

    // ---- load geometry ----
    const float* xp[2];
    char* sxa[2];
#pragma unroll
    for (int i = 0; i < 2; i++) {
        int r = (tid >> 3) + i * 32;   // 0..63
        int c = tid & 7;               // 0..7
        xp[i]  = x + (size_t)(t0 + r) * D_IN + c * 4;
        sxa[i] = sm + SM_AS + r * 80 + c * 8;
    }
    const __nv_bfloat16* wp[6];
    char* swb[6];
#pragma unroll
    for (int i = 0; i < 6; i++) {
        int idx = tid + i * 256;       // 0..1535
        int s = idx >> 9, rem = idx & 511;
        int r = rem >> 2, c = rem & 3;
        wp[i]  = g_W1s + s * (H_DIM * D_IN) + r * D_IN + c * 8;
        swb[i] = sm + SM_BS + s * BSPL + r * 80 + c * 16;
    }

    float4 xa[2];
    uint4  wb[6];
#pragma unroll
    for (int i = 0; i < 2; i++) xa[i] = *(const float4*)xp[i];
#pragma unroll
    for (int i = 0; i < 6; i++) wb[i] = *(const uint4*)wp[i];

    float accm[2][4][4];   // main-term fp32 RN accumulator
    float accc[2][4][4];   // correction-term MMA-chained accumulator
#pragma unroll
    for (int mt = 0; mt < 2; mt++)
#pragma unroll
        for (int nt = 0; nt < 4; nt++)
#pragma unroll
            for (int e = 0; e < 4; e++) {
                accm[mt][nt][e] = 0.0f;
                accc[mt][nt][e] = 0.0f;
            }

    char* abase[2];
    char* bbase[4];
#pragma unroll
    for (int mt = 0; mt < 2; mt++)
        abase[mt] = sm + SM_AS + (wm * 32 + mt * 16 + g) * 80 + tig * 4;
#pragma unroll
    for (int nt = 0; nt < 4; nt++)
        bbase[nt] = sm + SM_BS + (wn * 32 + nt * 8 + g) * 80 + tig * 4;

    // ---- mainloop: 32 K-chunks of 32 ----
    for (int ch = 0; ch < 32; ch++) {
        __syncthreads();   // previous tile fully consumed (and W2s writes done)
#pragma unroll
        for (int i = 0; i < 2; i++) {
            uint16_t a0, a1, a2, e0, e1, e2, c0, c1, c2, d0, d1, d2;
            split3(xa[i].x, a0, a1, a2);
            split3(xa[i].y, e0, e1, e2);
            split3(xa[i].z, c0, c1, c2);
            split3(xa[i].w, d0, d1, d2);
            *(uint2*)(sxa[i] + 0 * ASPL) = make_uint2(pack2(a0, e0), pack2(c0, d0));
            *(uint2*)(sxa[i] + 1 * ASPL) = make_uint2(pack2(a1, e1), pack2(c1, d1));
            *(uint2*)(sxa[i] + 2 * ASPL) = make_uint2(pack2(a2, e2), pack2(c2, d2));
        }
#pragma unroll
        for (int i = 0; i < 6; i++) *(uint4*)swb[i] = wb[i];
        __syncthreads();

        if (ch < 31) {
#pragma unroll
            for (int i = 0; i < 2; i++)
                xa[i] = *(const float4*)(xp[i] + (ch + 1) * 32);
#pragma unroll
            for (int i = 0; i < 6; i++)
                wb[i] = *(const uint4*)(wp[i] + (ch + 1) * 32);
        }

        // per-chunk zero-C accumulator for the main term
        float dm[2][4][4];
#pragma unroll
        for (int mt = 0; mt < 2; mt++)
#pragma unroll
            for (int nt = 0; nt < 4; nt++)
#pragma unroll
                for (int e = 0; e < 4; e++) dm[mt][nt][e] = 0.0f;

#pragma unroll
        for (int ks = 0; ks < 2; ks++) {
            uint32_t bf[3][4][2];
#pragma unroll
            for (int s = 0; s < 3; s++)
#pragma unroll
                for (int nt = 0; nt < 4; nt++) {
                    bf[s][nt][0] = *(const uint32_t*)(bbase[nt] + s * BSPL + ks * 32);
                    bf[s][nt][1] = *(const uint32_t*)(bbase[nt] + s * BSPL + ks * 32 + 16);
                }
            const int nb[3] = {3, 2, 1};   // terms: A0{B0,B1,B2} A1{B0,B1} A2{B0}
#pragma unroll
            for (int sa = 0; sa < 3; sa++) {
#pragma unroll
                for (int mt = 0; mt < 2; mt++) {
                    uint32_t af[4];
                    const char* ab = abase[mt] + sa * ASPL + ks * 32;
                    af[0] = *(const uint32_t*)(ab);
                    af[1] = *(const uint32_t*)(ab + 640);   // row +8
                    af[2] = *(const uint32_t*)(ab + 16);    // col +8
                    af[3] = *(const uint32_t*)(ab + 656);
#pragma unroll
                    for (int sb = 0; sb < 3; sb++) {
                        if (sb < nb[sa]) {
#pragma unroll
                            for (int nt = 0; nt < 4; nt++) {
                                if (sa == 0 && sb == 0)
                                    mma_bf16(dm[mt][nt], af, bf[0][nt]);
                                else
                                    mma_bf16(accc[mt][nt], af, bf[sb][nt]);
                            }
                        }
                    }
                }
            }
        }
        // drain main-term chunk sums with RN fp32 adds
#pragma unroll
        for (int mt = 0; mt < 2; mt++)
#pragma unroll
            for (int nt = 0; nt < 4; nt++)
#pragma unroll
                for (int e = 0; e < 4; e++)
                    accm[mt][nt][e] += dm[mt][nt][e];
    }

    // ---- epilogue 1: h = relu(C1 + b1) -> split into A2 tiles ----
    __syncthreads();   // all mma done before overwriting As/Bs region
#pragma unroll
    for (int mt = 0; mt < 2; mt++) {
        int r0 = wm * 32 + mt * 16 + g;
#pragma unroll
        for (int nt = 0; nt < 4; nt++) {
            int c0i = wn * 32 + nt * 8 + tig * 2;
            float h00 = fmaxf(accm[mt][nt][0] + accc[mt][nt][0] + b1s[c0i], 0.0f);
            float h01 = fmaxf(accm[mt][nt][1] + accc[mt][nt][1] + b1s[c0i + 1], 0.0f);
            float h10 = fmaxf(accm[mt][nt][2] + accc[mt][nt][2] + b1s[c0i], 0.0f);
            float h11 = fmaxf(accm[mt][nt][3] + accc[mt][nt][3] + b1s[c0i + 1], 0.0f);
            uint16_t p0, p1, p2, q0, q1, q2;
            split3(h00, p0, p1, p2);
            split3(h01, q0, q1, q2);
            char* ba = sm + SM_A2 + r0 * 272 + c0i * 2;
            *(uint32_t*)(ba + 0 * A2SPL) = pack2(p0, q0);
            *(uint32_t*)(ba + 1 * A2SPL) = pack2(p1, q1);
            *(uint32_t*)(ba + 2 * A2SPL) = pack2(p2, q2);
            split3(h10, p0, p1, p2);
            split3(h11, q0, q1, q2);
            char* bb = sm + SM_A2 + (r0 + 8) * 272 + c0i * 2;
            *(uint32_t*)(bb + 0 * A2SPL) = pack2(p0, q0);
            *(uint32_t*)(bb + 1 * A2SPL) = pack2(p1, q1);
            *(uint32_t*)(bb + 2 * A2SPL) = pack2(p2, q2);
        }
    }
    __syncthreads();

    // ---- GEMM2: q = h @ W2^T (warp tile m32 x n8, K=128) ----
    float accm2[2][4];
    float accc2[2][4];
#pragma unroll
    for (int mt = 0; mt < 2; mt++)
#pragma unroll
        for (int e = 0; e < 4; e++) {
            accm2[mt][e] = 0.0f;
            accc2[mt][e] = 0.0f;
        }

    char* a2base[2];
#pragma unroll
    for (int mt = 0; mt < 2; mt++)
        a2base[mt] = sm + SM_A2 + (wm * 32 + mt * 16 + g) * 272 + tig * 4;
    char* b2base = sm + SM_W2 + (wn * 8 + g) * 272 + tig * 4;

#pragma unroll
    for (int ks = 0; ks < 8; ks++) {
        uint32_t bf[3][2];
#pragma unroll
        for (int s = 0; s < 3; s++) {
            bf[s][0] = *(const uint32_t*)(b2base + s * W2SPL + ks * 32);
            bf[s][1] = *(const uint32_t*)(b2base + s * W2SPL + ks * 32 + 16);
        }
        float d2[2][4];
#pragma unroll
        for (int mt = 0; mt < 2; mt++)
#pragma unroll
            for (int e = 0; e < 4; e++) d2[mt][e] = 0.0f;

        const int nb[3] = {3, 2, 1};
#pragma unroll
        for (int sa = 0; sa < 3; sa++) {
#pragma unroll
            for (int mt = 0; mt < 2; mt++) {
                uint32_t af[4];
                const char* ab = a2base[mt] + sa * A2SPL + ks * 32;
                af[0] = *(const uint32_t*)(ab);
                af[1] = *(const uint32_t*)(ab + 2176);   // row +8 (stride 272)
                af[2] = *(const uint32_t*)(ab + 16);
                af[3] = *(const uint32_t*)(ab + 2192);
#pragma unroll
                for (int sb = 0; sb < 3; sb++) {
                    if (sb < nb[sa]) {
                        if (sa == 0 && sb == 0) mma_bf16(d2[mt], af, bf[0]);
                        else                    mma_bf16(accc2[mt], af, bf[sb]);
                    }
                }
            }
        }
#pragma unroll
        for (int mt = 0; mt < 2; mt++)
#pragma unroll
            for (int e = 0; e < 4; e++) accm2[mt][e] += d2[mt][e];
    }

    // ---- epilogue 2: q + b2 -> global ----
#pragma unroll
    for (int mt = 0; mt < 2; mt++) {
        int r0  = t0 + wm * 32 + mt * 16 + g;
        int c0i = wn * 8 + tig * 2;
        float2 v0 = make_float2(accm2[mt][0] + accc2[mt][0] + b2s[c0i],
                                accm2[mt][1] + accc2[mt][1] + b2s[c0i + 1]);
        float2 v1 = make_float2(accm2[mt][2] + accc2[mt][2] + b2s[c0i],
                                accm2[mt][3] + accc2[mt][3] + b2s[c0i + 1]);
        *(float2*)&g_q[(size_t)r0 * 32 + c0i]       = v0;
        *(float2*)&g_q[(size_t)(r0 + 8) * 32 + c0i] = v1;
    }
}

// ===========================================================================
// Selection + gather kernel (proven Round-2 logic)
// ===========================================================================
__device__ __forceinline__ unsigned fmap(float f) {
    unsigned u = __float_as_uint(f);
    return (u & 0x80000000u) ? ~u : (u | 0x80000000u);
}
__device__ __forceinline__ float funmap(unsigned m) {
    return (m & 0x80000000u) ? __uint_as_float(m & 0x7FFFFFFFu)
                             : __uint_as_float(~m);
}

__device__ __forceinline__ void topk8_256(float sv[8], int lane,
                                          float* top_s, int* top_i) {
    for (int k = 0; k < KNN; k++) {
        float best = sv[0];
        int bj = 0;
#pragma unroll
        for (int j = 1; j < 8; j++) {
            if (sv[j] > best) { best = sv[j]; bj = j; }
        }
        unsigned u = fmap(best);
        unsigned g = __reduce_max_sync(0xFFFFFFFFu, u);
        unsigned cand = (u == g) ? (unsigned)(lane + 32 * bj) : 0xFFFFFFFFu;
        unsigned nw = __reduce_min_sync(0xFFFFFFFFu, cand);
        if (lane == (int)(nw & 31u)) {
            int jw = (int)(nw >> 5);
#pragma unroll
            for (int j = 0; j < 8; j++) {
                if (j == jw) sv[j] = -FLT_MAX;
            }
        }
        if (lane == 0) { top_s[k] = funmap(g); top_i[k] = (int)nw; }
    }
}

#define TPB2 16   // tokens per block

__global__ __launch_bounds__(256, 4)
void select_gather_kernel(const float* __restrict__ keys,
                          const float* __restrict__ values,
                          float* __restrict__ out)
{
    __shared__ float keysb[1024 * 9];
    __shared__ float wss[TPB2 * 16];
    __shared__ int   idxs[TPB2 * 16];
    __shared__ float top_s[8 * 2 * 8];
    __shared__ int   top_i[8 * 2 * 8];

    const int tid  = threadIdx.x;
    const int lane = tid & 31;
    const int warp = tid >> 5;
    const int t0   = blockIdx.x * TPB2;

    for (int e = tid; e < HEADS * 2 * N_KEYS * HALF_D; e += 256) {
        keysb[(e >> 3) * 9 + (e & 7)] = keys[e];
    }
    __syncthreads();

    // 32 tasks (16 tokens x 2 heads), 8 warps, 4 tasks each
    for (int it = 0; it < 4; it++) {
        const int task = it * 8 + warp;
        const int tl = task >> 1;
        const int h  = task & 1;
        const int t  = t0 + tl;

        float q1r[8], q2r[8];
        const float* qrow = &g_q[(size_t)t * 32 + h * 16];
#pragma unroll
        for (int c = 0; c < 8; c++) {
            q1r[c] = __ldg(qrow + c);
            q2r[c] = __ldg(qrow + 8 + c);
        }

        float s1v[8], s2v[8];
        const float* k1 = &keysb[(h * 2 + 0) * N_KEYS * 9];
        const float* k2 = &keysb[(h * 2 + 1) * N_KEYS * 9];
#pragma unroll
        for (int j = 0; j < 8; j++) {
            const int n = lane + 32 * j;
            const float* kr1 = k1 + n * 9;
            const float* kr2 = k2 + n * 9;
            float a1 = 0.0f, a2 = 0.0f;
#pragma unroll
            for (int c = 0; c < 8; c++) {
                a1 += q1r[c] * kr1[c];
                a2 += q2r[c] * kr2[c];
            }
            s1v[j] = a1;
            s2v[j] = a2;
        }

        float* ts1 = &top_s[(warp * 2 + 0) * 8];
        float* ts2 = &top_s[(warp * 2 + 1) * 8];
        int*   ti1 = &top_i[(warp * 2 + 0) * 8];
        int*   ti2 = &top_i[(warp * 2 + 1) * 8];
        topk8_256(s1v, lane, ts1, ti1);
        topk8_256(s2v, lane, ts2, ti2);
        __syncwarp();

        const int a  = lane >> 2;
        const int b0 = (2 * lane) & 7;
        float cv0 = ts1[a] + ts2[b0];
        float cv1 = ts1[a] + ts2[b0 + 1];

        float ek[KNN];
        int   iks[KNN];
        float v0 = 0.0f, esum = 0.0f;
#pragma unroll
        for (int k = 0; k < KNN; k++) {
            float best;
            int slot;
            if (cv1 > cv0) { best = cv1; slot = 1; }
            else           { best = cv0; slot = 0; }
            unsigned u = fmap(best);
            unsigned g = __reduce_max_sync(0xFFFFFFFFu, u);
            unsigned cand = (u == g) ? (unsigned)(2 * lane + slot) : 0xFFFFFFFFu;
            unsigned jw = __reduce_min_sync(0xFFFFFFFFu, cand);
            float val = funmap(g);
            if (k == 0) v0 = val;
            float e = expf(val - v0);
            esum += e;
            if (lane == (int)(jw >> 1)) {
                if (jw & 1u) cv1 = -FLT_MAX;
                else         cv0 = -FLT_MAX;
            }
            if (lane == 0) {
                int aa = (int)(jw >> 3);
                int bb = (int)(jw & 7u);
                ek[k]  = e;
                iks[k] = ti1[aa] * N_KEYS + ti2[bb];
            }
        }
        if (lane == 0) {
#pragma unroll
            for (int k = 0; k < KNN; k++) {
                wss[tl * 16 + h * 8 + k]  = ek[k] / esum;
                idxs[tl * 16 + h * 8 + k] = iks[k];
            }
        }
        __syncwarp();
    }
    __syncthreads();

    // gather: out[t] = sum_k w * values[idx]
    const size_t c4 = (size_t)tid * 4;   // 256 threads x float4 = 1024 cols
    for (int tl = 0; tl < TPB2; tl++) {
        float4 acc = make_float4(0.0f, 0.0f, 0.0f, 0.0f);
#pragma unroll
        for (int k = 0; k < 16; k++) {
            const float wk = wss[tl * 16 + k];
            const int row  = idxs[tl * 16 + k];
            const float4 v = *reinterpret_cast<const float4*>(
                &values[((size_t)row << 10) + c4]);
            acc.x += wk * v.x;
            acc.y += wk * v.y;
            acc.z += wk * v.z;
            acc.w += wk * v.w;
        }
        *reinterpret_cast<float4*>(&out[((size_t)(t0 + tl) << 10) + c4]) = acc;
    }
}

// ===========================================================================
// Launch
// ===========================================================================
extern "C" void kernel_launch(void* const* d_in, const int* in_sizes, int n_in,
                              void* d_out, int out_size) {
    const float* x      = (const float*)d_in[0];
    const float* W1     = (const float*)d_in[1];
    const float* b1     = (const float*)d_in[2];
    const float* W2     = (const float*)d_in[3];
    const float* b2     = (const float*)d_in[4];
    const float* keys   = (const float*)d_in[5];
    const float* values = (const float*)d_in[6];
    float* out = (float*)d_out;

    const int T = in_sizes[0] / D_IN;   // 8192

    cudaFuncSetAttribute(gemm_kernel,
                         cudaFuncAttributeMaxDynamicSharedMemorySize,
                         SMEM_GEMM_BYTES);

    split_w1_kernel<<<H_DIM * D_IN / 4 / 256, 256>>>(W1);
    gemm_kernel<<<T / 64, 256, SMEM_GEMM_BYTES>>>(x, b1, W2, b2);
    select_gather_kernel<<<T / TPB2, 256>>>(keys, values, out);
}

// round 6
// speedup vs baseline: 1.5115x; 1.0345x over previous
#include <cuda_runtime.h>
#include <cuda_bf16.h>
#include <math.h>
#include <float.h>
#include <stdint.h>

// Problem constants
#define HEADS   2
#define K_DIM   16
#define HALF_D  8
#define KNN     8
#define N_KEYS  256
#define D_IN    1024
#define H_DIM   128

// Global scratch
__device__ float g_q[8192 * 32];                         // q: [T][32]
__device__ __nv_bfloat16 g_W1s[3 * H_DIM * D_IN];        // W1 3-way bf16 split

// ---------------------------------------------------------------------------
// 3-way bf16 split of fp32 (sum of 3 bf16 ~= fp32)
// ---------------------------------------------------------------------------
__device__ __forceinline__ void split3(float a, uint16_t& u0, uint16_t& u1,
                                       uint16_t& u2) {
    __nv_bfloat16 h0 = __float2bfloat16(a);
    float r1 = a - __bfloat162float(h0);
    __nv_bfloat16 h1 = __float2bfloat16(r1);
    float r2 = r1 - __bfloat162float(h1);
    __nv_bfloat16 h2 = __float2bfloat16(r2);
    u0 = __bfloat16_as_ushort(h0);
    u1 = __bfloat16_as_ushort(h1);
    u2 = __bfloat16_as_ushort(h2);
}
__device__ __forceinline__ uint32_t pack2(uint16_t lo, uint16_t hi) {
    return (uint32_t)lo | ((uint32_t)hi << 16);
}

__device__ __forceinline__ void mma_bf16(float* c, const uint32_t* a,
                                         const uint32_t* b) {
    asm volatile(
        "mma.sync.aligned.m16n8k16.row.col.f32.bf16.bf16.f32 "
        "{%0,%1,%2,%3}, {%4,%5,%6,%7}, {%8,%9}, {%0,%1,%2,%3};"
        : "+f"(c[0]), "+f"(c[1]), "+f"(c[2]), "+f"(c[3])
        : "r"(a[0]), "r"(a[1]), "r"(a[2]), "r"(a[3]), "r"(b[0]), "r"(b[1]));
}

__device__ __forceinline__ uint32_t smem_u32(const void* p) {
    uint32_t a;
    asm("{ .reg .u64 t; cvta.to.shared.u64 t, %1; cvt.u32.u64 %0, t; }"
        : "=r"(a) : "l"(p));
    return a;
}

__device__ __forceinline__ void ldsm_x4(uint32_t* r, uint32_t addr) {
    asm volatile(
        "ldmatrix.sync.aligned.m8n8.x4.shared.b16 {%0,%1,%2,%3}, [%4];"
        : "=r"(r[0]), "=r"(r[1]), "=r"(r[2]), "=r"(r[3]) : "r"(addr));
}

// ---------------------------------------------------------------------------
// Kernel 0: pre-split W1 [128][1024] f32 -> g_W1s[3][128][1024] bf16
// ---------------------------------------------------------------------------
__global__ void split_w1_kernel(const float* __restrict__ W1) {
    int idx4 = blockIdx.x * 256 + threadIdx.x;    // over 32768 float4
    float4 v = ((const float4*)W1)[idx4];
    uint16_t a0, a1, a2, b0, b1, b2, c0, c1, c2, d0, d1, d2;
    split3(v.x, a0, a1, a2);
    split3(v.y, b0, b1, b2);
    split3(v.z, c0, c1, c2);
    split3(v.w, d0, d1, d2);
    uint2* o = (uint2*)g_W1s;
    o[0 * 32768 + idx4] = make_uint2(pack2(a0, b0), pack2(c0, d0));
    o[1 * 32768 + idx4] = make_uint2(pack2(a1, b1), pack2(c1, d1));
    o[2 * 32768 + idx4] = make_uint2(pack2(a2, b2), pack2(c2, d2));
}

// ---------------------------------------------------------------------------
// GEMM kernel: q = relu(x @ W1^T + b1) @ W2^T + b2  via mma.sync (3x-bf16)
// CTA = 64 tokens, 256 threads (8 warps: 2m x 4n), BK = 32, double-buffered.
//
// Tensor-core fp32 accumulate is RZ: main (A0*B0) term uses zero-init C per
// 32-wide K-chunk drained with RN adds; small correction terms chain in MMA.
//
// smem byte map:
//   [0, 1024)            b1s (128 f32) @0, b2s (32 f32) @512
//   [1024, 31744)        As[2 stages][3 splits][64][40] bf16 (row 80B)
//   [31744, 93184)       Bs[2 stages][3 splits][128][40] bf16
//   [93184, 119296)      W2s[3][32][136] bf16
//   -- union after GEMM1: [1024, 53248) A2[3][64][136] bf16 --
// ---------------------------------------------------------------------------
#define ASPL     5120      // 64*80
#define BSPL     10240     // 128*80
#define AST      15360     // stage stride A = 3*ASPL
#define BST      30720     // stage stride B = 3*BSPL
#define SM_AS0   1024
#define SM_BS0   31744
#define SM_W2    93184
#define W2SPL    8704      // 32*272
#define SM_A2    1024
#define A2SPL    17408     // 64*272
#define SMEM_GEMM_BYTES 119296

__global__ __launch_bounds__(256, 1)
void gemm_kernel(const float* __restrict__ x, const float* __restrict__ b1,
                 const float* __restrict__ W2, const float* __restrict__ b2)
{
    extern __shared__ char sm[];
    const uint32_t sbase = smem_u32(sm);
    float* b1s = (float*)(sm);
    float* b2s = (float*)(sm + 512);

    const int tid  = threadIdx.x;
    const int lane = tid & 31;
    const int warp = tid >> 5;
    const int g    = lane >> 2;      // fragment group row
    const int tig  = lane & 3;       // thread-in-group
    const int wm   = warp >> 2;      // 0..1 (m)
    const int wn   = warp & 3;       // 0..3 (n)
    const int t0   = blockIdx.x * 64;

    if (tid < 128) b1s[tid] = b1[tid];
    if (tid < 32)  b2s[tid] = b2[tid];

    // ---- W2 [32][128] -> split tiles W2s[3][32][136] ----
#pragma unroll
    for (int i = 0; i < 4; i++) {
        int idx4 = tid + i * 256;          // 1024 float4
        int n  = idx4 >> 5;
        int c4 = idx4 & 31;
        float4 v = *(const float4*)(W2 + n * H_DIM + c4 * 4);
        uint16_t a0, a1, a2, e0, e1, e2, c0, c1, c2, d0, d1, d2;
        split3(v.x, a0, a1, a2);
        split3(v.y, e0, e1, e2);
        split3(v.z, c0, c1, c2);
        split3(v.w, d0, d1, d2);
        char* base = sm + SM_W2 + n * 272 + c4 * 8;
        *(uint2*)(base + 0 * W2SPL) = make_uint2(pack2(a0, e0), pack2(c0, d0));
        *(uint2*)(base + 1 * W2SPL) = make_uint2(pack2(a1, e1), pack2(c1, d1));
        *(uint2*)(base + 2 * W2SPL) = make_uint2(pack2(a2, e2), pack2(c2, d2));
    }

    // ---- load geometry (global pointers + in-stage store offsets) ----
    const float* xp[2];
    uint32_t sxa_off[2];               // offset within a stage's A split-0
#pragma unroll
    for (int i = 0; i < 2; i++) {
        int r = (tid >> 3) + i * 32;   // 0..63
        int c = tid & 7;               // 0..7
        xp[i]      = x + (size_t)(t0 + r) * D_IN + c * 4;
        sxa_off[i] = (uint32_t)(r * 80 + c * 8);
    }
    const __nv_bfloat16* wp[6];
    uint32_t swb_off[6];               // offset within a stage's B region
#pragma unroll
    for (int i = 0; i < 6; i++) {
        int idx = tid + i * 256;       // 0..1535
        int s = idx >> 9, rem = idx & 511;
        int r = rem >> 2, c = rem & 3;
        wp[i]      = g_W1s + s * (H_DIM * D_IN) + r * D_IN + c * 8;
        swb_off[i] = (uint32_t)(s * BSPL + r * 80 + c * 16);
    }

    // ---- ldmatrix per-lane address offsets ----
    const int r8   = lane & 7;
    const int quad = lane >> 3;        // 0..3
    uint32_t a_off[2];                 // per mt: within (stage, split) A region
#pragma unroll
    for (int mt = 0; mt < 2; mt++)
        a_off[mt] = (uint32_t)((wm * 32 + mt * 16 + ((quad & 1) ? 8 : 0) + r8) * 80
                               + ((quad >> 1) ? 16 : 0));
    uint32_t b_off[2];                 // per nt-pair p: within (stage, split) B region
#pragma unroll
    for (int p = 0; p < 2; p++)
        b_off[p] = (uint32_t)((wn * 32 + p * 16 + ((quad >> 1) ? 8 : 0) + r8) * 80
                              + ((quad & 1) ? 16 : 0));

    float4 xa[2];
    uint4  wb[6];
#pragma unroll
    for (int i = 0; i < 2; i++) xa[i] = *(const float4*)xp[i];
#pragma unroll
    for (int i = 0; i < 6; i++) wb[i] = *(const uint4*)wp[i];

    float accm[2][4][4];   // main-term fp32 RN accumulator
    float accc[2][4][4];   // correction-term MMA-chained accumulator
#pragma unroll
    for (int mt = 0; mt < 2; mt++)
#pragma unroll
        for (int nt = 0; nt < 4; nt++)
#pragma unroll
            for (int e = 0; e < 4; e++) {
                accm[mt][nt][e] = 0.0f;
                accc[mt][nt][e] = 0.0f;
            }

    // ---- prologue: store chunk 0 into stage 0 ----
    {
#pragma unroll
        for (int i = 0; i < 2; i++) {
            uint16_t a0, a1, a2, e0, e1, e2, c0, c1, c2, d0, d1, d2;
            split3(xa[i].x, a0, a1, a2);
            split3(xa[i].y, e0, e1, e2);
            split3(xa[i].z, c0, c1, c2);
            split3(xa[i].w, d0, d1, d2);
            char* ba = sm + SM_AS0 + sxa_off[i];
            *(uint2*)(ba + 0 * ASPL) = make_uint2(pack2(a0, e0), pack2(c0, d0));
            *(uint2*)(ba + 1 * ASPL) = make_uint2(pack2(a1, e1), pack2(c1, d1));
            *(uint2*)(ba + 2 * ASPL) = make_uint2(pack2(a2, e2), pack2(c2, d2));
        }
#pragma unroll
        for (int i = 0; i < 6; i++)
            *(uint4*)(sm + SM_BS0 + swb_off[i]) = wb[i];
    }
    __syncthreads();

    // ---- mainloop: 32 K-chunks of 32, double-buffered ----
    for (int ch = 0; ch < 32; ch++) {
        const int st = ch & 1;
        const uint32_t a_stage = sbase + SM_AS0 + (uint32_t)st * AST;
        const uint32_t b_stage = sbase + SM_BS0 + (uint32_t)st * BST;

        if (ch < 31) {
#pragma unroll
            for (int i = 0; i < 2; i++)
                xa[i] = *(const float4*)(xp[i] + (ch + 1) * 32);
#pragma unroll
            for (int i = 0; i < 6; i++)
                wb[i] = *(const uint4*)(wp[i] + (ch + 1) * 32);
        }

        // per-chunk zero-C accumulator for the main term
        float dm[2][4][4];
#pragma unroll
        for (int mt = 0; mt < 2; mt++)
#pragma unroll
            for (int nt = 0; nt < 4; nt++)
#pragma unroll
                for (int e = 0; e < 4; e++) dm[mt][nt][e] = 0.0f;

#pragma unroll
        for (int ks = 0; ks < 2; ks++) {
            uint32_t bf[3][4][2];
#pragma unroll
            for (int s = 0; s < 3; s++)
#pragma unroll
                for (int p = 0; p < 2; p++) {
                    uint32_t r4[4];
                    ldsm_x4(r4, b_stage + (uint32_t)s * BSPL + b_off[p]
                                 + (uint32_t)ks * 32);
                    bf[s][2 * p + 0][0] = r4[0];
                    bf[s][2 * p + 0][1] = r4[1];
                    bf[s][2 * p + 1][0] = r4[2];
                    bf[s][2 * p + 1][1] = r4[3];
                }
            const int nb[3] = {3, 2, 1};   // terms: A0{B0,B1,B2} A1{B0,B1} A2{B0}
#pragma unroll
            for (int sa = 0; sa < 3; sa++) {
#pragma unroll
                for (int mt = 0; mt < 2; mt++) {
                    uint32_t af[4];
                    ldsm_x4(af, a_stage + (uint32_t)sa * ASPL + a_off[mt]
                                 + (uint32_t)ks * 32);
#pragma unroll
                    for (int sb = 0; sb < 3; sb++) {
                        if (sb < nb[sa]) {
#pragma unroll
                            for (int nt = 0; nt < 4; nt++) {
                                if (sa == 0 && sb == 0)
                                    mma_bf16(dm[mt][nt], af, bf[0][nt]);
                                else
                                    mma_bf16(accc[mt][nt], af, bf[sb][nt]);
                            }
                        }
                    }
                }
            }
        }
        // drain main-term chunk sums with RN fp32 adds
#pragma unroll
        for (int mt = 0; mt < 2; mt++)
#pragma unroll
            for (int nt = 0; nt < 4; nt++)
#pragma unroll
                for (int e = 0; e < 4; e++)
                    accm[mt][nt][e] += dm[mt][nt][e];

        if (ch < 31) {
            const int nst = st ^ 1;
            char* astage = sm + SM_AS0 + nst * AST;
            char* bstage = sm + SM_BS0 + nst * BST;
#pragma unroll
            for (int i = 0; i < 2; i++) {
                uint16_t a0, a1, a2, e0, e1, e2, c0, c1, c2, d0, d1, d2;
                split3(xa[i].x, a0, a1, a2);
                split3(xa[i].y, e0, e1, e2);
                split3(xa[i].z, c0, c1, c2);
                split3(xa[i].w, d0, d1, d2);
                char* ba = astage + sxa_off[i];
                *(uint2*)(ba + 0 * ASPL) = make_uint2(pack2(a0, e0), pack2(c0, d0));
                *(uint2*)(ba + 1 * ASPL) = make_uint2(pack2(a1, e1), pack2(c1, d1));
                *(uint2*)(ba + 2 * ASPL) = make_uint2(pack2(a2, e2), pack2(c2, d2));
            }
#pragma unroll
            for (int i = 0; i < 6; i++)
                *(uint4*)(bstage + swb_off[i]) = wb[i];
        }
        __syncthreads();
    }

    // ---- epilogue 1: h = relu(C1 + b1) -> split into A2 tiles ----
#pragma unroll
    for (int mt = 0; mt < 2; mt++) {
        int r0 = wm * 32 + mt * 16 + g;
#pragma unroll
        for (int nt = 0; nt < 4; nt++) {
            int c0i = wn * 32 + nt * 8 + tig * 2;
            float h00 = fmaxf(accm[mt][nt][0] + accc[mt][nt][0] + b1s[c0i], 0.0f);
            float h01 = fmaxf(accm[mt][nt][1] + accc[mt][nt][1] + b1s[c0i + 1], 0.0f);
            float h10 = fmaxf(accm[mt][nt][2] + accc[mt][nt][2] + b1s[c0i], 0.0f);
            float h11 = fmaxf(accm[mt][nt][3] + accc[mt][nt][3] + b1s[c0i + 1], 0.0f);
            uint16_t p0, p1, p2, q0, q1, q2;
            split3(h00, p0, p1, p2);
            split3(h01, q0, q1, q2);
            char* ba = sm + SM_A2 + r0 * 272 + c0i * 2;
            *(uint32_t*)(ba + 0 * A2SPL) = pack2(p0, q0);
            *(uint32_t*)(ba + 1 * A2SPL) = pack2(p1, q1);
            *(uint32_t*)(ba + 2 * A2SPL) = pack2(p2, q2);
            split3(h10, p0, p1, p2);
            split3(h11, q0, q1, q2);
            char* bb = sm + SM_A2 + (r0 + 8) * 272 + c0i * 2;
            *(uint32_t*)(bb + 0 * A2SPL) = pack2(p0, q0);
            *(uint32_t*)(bb + 1 * A2SPL) = pack2(p1, q1);
            *(uint32_t*)(bb + 2 * A2SPL) = pack2(p2, q2);
        }
    }
    __syncthreads();

    // ---- GEMM2: q = h @ W2^T (warp tile m32 x n8, K=128) ----
    float accm2[2][4];
    float accc2[2][4];
#pragma unroll
    for (int mt = 0; mt < 2; mt++)
#pragma unroll
        for (int e = 0; e < 4; e++) {
            accm2[mt][e] = 0.0f;
            accc2[mt][e] = 0.0f;
        }

    char* a2base[2];
#pragma unroll
    for (int mt = 0; mt < 2; mt++)
        a2base[mt] = sm + SM_A2 + (wm * 32 + mt * 16 + g) * 272 + tig * 4;
    char* b2base = sm + SM_W2 + (wn * 8 + g) * 272 + tig * 4;

#pragma unroll
    for (int ks = 0; ks < 8; ks++) {
        uint32_t bf[3][2];
#pragma unroll
        for (int s = 0; s < 3; s++) {
            bf[s][0] = *(const uint32_t*)(b2base + s * W2SPL + ks * 32);
            bf[s][1] = *(const uint32_t*)(b2base + s * W2SPL + ks * 32 + 16);
        }
        float d2[2][4];
#pragma unroll
        for (int mt = 0; mt < 2; mt++)
#pragma unroll
            for (int e = 0; e < 4; e++) d2[mt][e] = 0.0f;

        const int nb[3] = {3, 2, 1};
#pragma unroll
        for (int sa = 0; sa < 3; sa++) {
#pragma unroll
            for (int mt = 0; mt < 2; mt++) {
                uint32_t af[4];
                const char* ab = a2base[mt] + sa * A2SPL + ks * 32;
                af[0] = *(const uint32_t*)(ab);
                af[1] = *(const uint32_t*)(ab + 2176);   // row +8 (stride 272)
                af[2] = *(const uint32_t*)(ab + 16);
                af[3] = *(const uint32_t*)(ab + 2192);
#pragma unroll
                for (int sb = 0; sb < 3; sb++) {
                    if (sb < nb[sa]) {
                        if (sa == 0 && sb == 0) mma_bf16(d2[mt], af, bf[0]);
                        else                    mma_bf16(accc2[mt], af, bf[sb]);
                    }
                }
            }
        }
#pragma unroll
        for (int mt = 0; mt < 2; mt++)
#pragma unroll
            for (int e = 0; e < 4; e++) accm2[mt][e] += d2[mt][e];
    }

    // ---- epilogue 2: q + b2 -> global ----
#pragma unroll
    for (int mt = 0; mt < 2; mt++) {
        int r0  = t0 + wm * 32 + mt * 16 + g;
        int c0i = wn * 8 + tig * 2;
        float2 v0 = make_float2(accm2[mt][0] + accc2[mt][0] + b2s[c0i],
                                accm2[mt][1] + accc2[mt][1] + b2s[c0i + 1]);
        float2 v1 = make_float2(accm2[mt][2] + accc2[mt][2] + b2s[c0i],
                                accm2[mt][3] + accc2[mt][3] + b2s[c0i + 1]);
        *(float2*)&g_q[(size_t)r0 * 32 + c0i]       = v0;
        *(float2*)&g_q[(size_t)(r0 + 8) * 32 + c0i] = v1;
    }
}

// ===========================================================================
// Selection + gather kernel (proven logic, unchanged)
// ===========================================================================
__device__ __forceinline__ unsigned fmap(float f) {
    unsigned u = __float_as_uint(f);
    return (u & 0x80000000u) ? ~u : (u | 0x80000000u);
}
__device__ __forceinline__ float funmap(unsigned m) {
    return (m & 0x80000000u) ? __uint_as_float(m & 0x7FFFFFFFu)
                             : __uint_as_float(~m);
}

__device__ __forceinline__ void topk8_256(float sv[8], int lane,
                                          float* top_s, int* top_i) {
    for (int k = 0; k < KNN; k++) {
        float best = sv[0];
        int bj = 0;
#pragma unroll
        for (int j = 1; j < 8; j++) {
            if (sv[j] > best) { best = sv[j]; bj = j; }
        }
        unsigned u = fmap(best);
        unsigned g = __reduce_max_sync(0xFFFFFFFFu, u);
        unsigned cand = (u == g) ? (unsigned)(lane + 32 * bj) : 0xFFFFFFFFu;
        unsigned nw = __reduce_min_sync(0xFFFFFFFFu, cand);
        if (lane == (int)(nw & 31u)) {
            int jw = (int)(nw >> 5);
#pragma unroll
            for (int j = 0; j < 8; j++) {
                if (j == jw) sv[j] = -FLT_MAX;
            }
        }
        if (lane == 0) { top_s[k] = funmap(g); top_i[k] = (int)nw; }
    }
}

#define TPB2 16   // tokens per block

__global__ __launch_bounds__(256, 4)
void select_gather_kernel(const float* __restrict__ keys,
                          const float* __restrict__ values,
                          float* __restrict__ out)
{
    __shared__ float keysb[1024 * 9];
    __shared__ float wss[TPB2 * 16];
    __shared__ int   idxs[TPB2 * 16];
    __shared__ float top_s[8 * 2 * 8];
    __shared__ int   top_i[8 * 2 * 8];

    const int tid  = threadIdx.x;
    const int lane = tid & 31;
    const int warp = tid >> 5;
    const int t0   = blockIdx.x * TPB2;

    for (int e = tid; e < HEADS * 2 * N_KEYS * HALF_D; e += 256) {
        keysb[(e >> 3) * 9 + (e & 7)] = keys[e];
    }
    __syncthreads();

    // 32 tasks (16 tokens x 2 heads), 8 warps, 4 tasks each
    for (int it = 0; it < 4; it++) {
        const int task = it * 8 + warp;
        const int tl = task >> 1;
        const int h  = task & 1;
        const int t  = t0 + tl;

        float q1r[8], q2r[8];
        const float* qrow = &g_q[(size_t)t * 32 + h * 16];
#pragma unroll
        for (int c = 0; c < 8; c++) {
            q1r[c] = __ldg(qrow + c);
            q2r[c] = __ldg(qrow + 8 + c);
        }

        float s1v[8], s2v[8];
        const float* k1 = &keysb[(h * 2 + 0) * N_KEYS * 9];
        const float* k2 = &keysb[(h * 2 + 1) * N_KEYS * 9];
#pragma unroll
        for (int j = 0; j < 8; j++) {
            const int n = lane + 32 * j;
            const float* kr1 = k1 + n * 9;
            const float* kr2 = k2 + n * 9;
            float a1 = 0.0f, a2 = 0.0f;
#pragma unroll
            for (int c = 0; c < 8; c++) {
                a1 += q1r[c] * kr1[c];
                a2 += q2r[c] * kr2[c];
            }
            s1v[j] = a1;
            s2v[j] = a2;
        }

        float* ts1 = &top_s[(warp * 2 + 0) * 8];
        float* ts2 = &top_s[(warp * 2 + 1) * 8];
        int*   ti1 = &top_i[(warp * 2 + 0) * 8];
        int*   ti2 = &top_i[(warp * 2 + 1) * 8];
        topk8_256(s1v, lane, ts1, ti1);
        topk8_256(s2v, lane, ts2, ti2);
        __syncwarp();

        const int a  = lane >> 2;
        const int b0 = (2 * lane) & 7;
        float cv0 = ts1[a] + ts2[b0];
        float cv1 = ts1[a] + ts2[b0 + 1];

        float ek[KNN];
        int   iks[KNN];
        float v0 = 0.0f, esum = 0.0f;
#pragma unroll
        for (int k = 0; k < KNN; k++) {
            float best;
            int slot;
            if (cv1 > cv0) { best = cv1; slot = 1; }
            else           { best = cv0; slot = 0; }
            unsigned u = fmap(best);
            unsigned g = __reduce_max_sync(0xFFFFFFFFu, u);
            unsigned cand = (u == g) ? (unsigned)(2 * lane + slot) : 0xFFFFFFFFu;
            unsigned jw = __reduce_min_sync(0xFFFFFFFFu, cand);
            float val = funmap(g);
            if (k == 0) v0 = val;
            float e = expf(val - v0);
            esum += e;
            if (lane == (int)(jw >> 1)) {
                if (jw & 1u) cv1 = -FLT_MAX;
                else         cv0 = -FLT_MAX;
            }
            if (lane == 0) {
                int aa = (int)(jw >> 3);
                int bb = (int)(jw & 7u);
                ek[k]  = e;
                iks[k] = ti1[aa] * N_KEYS + ti2[bb];
            }
        }
        if (lane == 0) {
#pragma unroll
            for (int k = 0; k < KNN; k++) {
                wss[tl * 16 + h * 8 + k]  = ek[k] / esum;
                idxs[tl * 16 + h * 8 + k] = iks[k];
            }
        }
        __syncwarp();
    }
    __syncthreads();

    // gather: out[t] = sum_k w * values[idx]
    const size_t c4 = (size_t)tid * 4;   // 256 threads x float4 = 1024 cols
    for (int tl = 0; tl < TPB2; tl++) {
        float4 acc = make_float4(0.0f, 0.0f, 0.0f, 0.0f);
#pragma unroll
        for (int k = 0; k < 16; k++) {
            const float wk = wss[tl * 16 + k];
            const int row  = idxs[tl * 16 + k];
            const float4 v = *reinterpret_cast<const float4*>(
                &values[((size_t)row << 10) + c4]);
            acc.x += wk * v.x;
            acc.y += wk * v.y;
            acc.z += wk * v.z;
            acc.w += wk * v.w;
        }
        *reinterpret_cast<float4*>(&out[((size_t)(t0 + tl) << 10) + c4]) = acc;
    }
}

// ===========================================================================
// Launch
// ===========================================================================
extern "C" void kernel_launch(void* const* d_in, const int* in_sizes, int n_in,
                              void* d_out, int out_size) {
    const float* x      = (const float*)d_in[0];
    const float* W1     = (const float*)d_in[1];
    const float* b1     = (const float*)d_in[2];
    const float* W2     = (const float*)d_in[3];
    const float* b2     = (const float*)d_in[4];
    const float* keys   = (const float*)d_in[5];
    const float* values = (const float*)d_in[6];
    float* out = (float*)d_out;

    const int T = in_sizes[0] / D_IN;   // 8192

    cudaFuncSetAttribute(gemm_kernel,
                         cudaFuncAttributeMaxDynamicSharedMemorySize,
                         SMEM_GEMM_BYTES);

    split_w1_kernel<<<H_DIM * D_IN / 4 / 256, 256>>>(W1);
    gemm_kernel<<<T / 64, 256, SMEM_GEMM_BYTES>>>(x, b1, W2, b2);
    select_gather_kernel<<<T / TPB2, 256>>>(keys, values, out);
}

// round 7
// speedup vs baseline: 1.5217x; 1.0067x over previous
#include <cuda_runtime.h>
#include <cuda_bf16.h>
#include <math.h>
#include <float.h>
#include <stdint.h>

// Problem constants
#define HEADS   2
#define K_DIM   16
#define HALF_D  8
#define KNN     8
#define N_KEYS  256
#define D_IN    1024
#define H_DIM   128

// Global scratch
__device__ float    g_q[8192 * 32];                 // q: [T][32]
__device__ uint32_t g_W1sp[2 * H_DIM * D_IN];       // W1 tf32 2-split (t0, t1)

// ---------------------------------------------------------------------------
// tf32 helpers: a ~= t0 + t1, each tf32 (11-bit mantissa); dropped t1*t1 ~ 2^-24
// ---------------------------------------------------------------------------
__device__ __forceinline__ uint32_t cvt_tf32(float a) {
    uint32_t u;
    asm("cvt.rna.tf32.f32 %0, %1;" : "=r"(u) : "f"(a));
    return u;
}
__device__ __forceinline__ void split2(float a, uint32_t& t0, uint32_t& t1) {
    t0 = cvt_tf32(a);
    t1 = cvt_tf32(a - __uint_as_float(t0));
}

__device__ __forceinline__ void mma_tf32(float* c, const uint32_t* a,
                                         const uint32_t* b) {
    asm volatile(
        "mma.sync.aligned.m16n8k8.row.col.f32.tf32.tf32.f32 "
        "{%0,%1,%2,%3}, {%4,%5,%6,%7}, {%8,%9}, {%0,%1,%2,%3};"
        : "+f"(c[0]), "+f"(c[1]), "+f"(c[2]), "+f"(c[3])
        : "r"(a[0]), "r"(a[1]), "r"(a[2]), "r"(a[3]), "r"(b[0]), "r"(b[1]));
}

// ---------------------------------------------------------------------------
// Kernel 0: pre-split W1 [128][1024] f32 -> g_W1sp[2][128][1024] tf32-as-u32
// ---------------------------------------------------------------------------
__global__ void split_w1_kernel(const float* __restrict__ W1) {
    int idx4 = blockIdx.x * 256 + threadIdx.x;    // over 32768 float4
    float4 v = ((const float4*)W1)[idx4];
    uint4 t0, t1;
    split2(v.x, t0.x, t1.x);
    split2(v.y, t0.y, t1.y);
    split2(v.z, t0.z, t1.z);
    split2(v.w, t0.w, t1.w);
    ((uint4*)g_W1sp)[idx4]         = t0;
    ((uint4*)g_W1sp)[32768 + idx4] = t1;
}

// ---------------------------------------------------------------------------
// GEMM kernel: q = relu(x @ W1^T + b1) @ W2^T + b2  via mma.sync tf32 (2-split)
// CTA = 64 tokens, 256 threads (8 warps: 2m x 4n), BK = 32, double-buffered.
//
// Terms per product: T0 = A0*B0 (per-chunk zero-C, RN drain — avoids the
// tensor-core RZ accumulation bias), T1 = A0*B1 + A1*B0 (chained, ~2^-12).
// Dropped A1*B1 ~ 2^-24 relative.
//
// smem (bytes):
//   [0,512) b1s; [512,640) b2s
//   A stages: [1024, +2*18432)   2 stages x 2 splits x 64 rows x 144B
//   B stages: [37888, +2*36864)  2 stages x 2 splits x 128 rows x 144B
//   W2 tiles: [111616, +33792)   2 splits x 32 rows x 528B
//   A2 union: [1024, +67584)     2 splits x 64 rows x 528B (after GEMM1)
// Row strides 36 / 132 words (== 4 mod 32) -> conflict-free fragment LDS.
// ---------------------------------------------------------------------------
#define ASPL     9216      // 64*144
#define BSPL     18432     // 128*144
#define AST      18432     // stage stride A = 2*ASPL
#define BST      36864     // stage stride B = 2*BSPL
#define SM_AS0   1024
#define SM_BS0   37888
#define SM_W2    111616
#define W2SPL    16896     // 32*528
#define SM_A2    1024
#define A2SPL    33792     // 64*528
#define SMEM_GEMM_BYTES 145408

__global__ __launch_bounds__(256, 1)
void gemm_kernel(const float* __restrict__ x, const float* __restrict__ b1,
                 const float* __restrict__ W2, const float* __restrict__ b2)
{
    extern __shared__ char sm[];
    float* b1s = (float*)(sm);
    float* b2s = (float*)(sm + 512);

    const int tid  = threadIdx.x;
    const int lane = tid & 31;
    const int warp = tid >> 5;
    const int g    = lane >> 2;      // fragment group row
    const int tig  = lane & 3;       // thread-in-group
    const int wm   = warp >> 2;      // 0..1 (m)
    const int wn   = warp & 3;       // 0..3 (n)
    const int t0b  = blockIdx.x * 64;

    if (tid < 128) b1s[tid] = b1[tid];
    if (tid < 32)  b2s[tid] = b2[tid];

    // ---- W2 [32][128] -> tf32 split tiles W2s[2][32][132] ----
#pragma unroll
    for (int i = 0; i < 4; i++) {
        int idx4 = tid + i * 256;          // 1024 float4
        int n  = idx4 >> 5;
        int c4 = idx4 & 31;
        float4 v = *(const float4*)(W2 + n * H_DIM + c4 * 4);
        uint4 u0, u1;
        split2(v.x, u0.x, u1.x);
        split2(v.y, u0.y, u1.y);
        split2(v.z, u0.z, u1.z);
        split2(v.w, u0.w, u1.w);
        char* base = sm + SM_W2 + n * 528 + c4 * 16;
        *(uint4*)(base + 0 * W2SPL) = u0;
        *(uint4*)(base + 1 * W2SPL) = u1;
    }

    // ---- load geometry ----
    const float* xp[2];
    uint32_t sxa_off[2];               // within a stage's split-0 A region
#pragma unroll
    for (int i = 0; i < 2; i++) {
        int r = (tid >> 3) + i * 32;   // 0..63
        int c = tid & 7;               // float4 col 0..7
        xp[i]      = x + (size_t)(t0b + r) * D_IN + c * 4;
        sxa_off[i] = (uint32_t)(r * 144 + c * 16);
    }
    const uint32_t* wp[8];
    uint32_t swb_off[8];               // within a stage's B region
#pragma unroll
    for (int i = 0; i < 8; i++) {
        int idx = tid + i * 256;       // 0..2047 over 2 splits x 128 rows x 8 f4
        int s = idx >> 10, rem = idx & 1023;
        int r = rem >> 3, c = rem & 7;
        wp[i]      = g_W1sp + s * (H_DIM * D_IN) + r * D_IN + c * 4;
        swb_off[i] = (uint32_t)(s * BSPL + r * 144 + c * 16);
    }

    // ---- fragment byte offsets (within stage+split regions) ----
    uint32_t a_off[2];
#pragma unroll
    for (int mt = 0; mt < 2; mt++)
        a_off[mt] = (uint32_t)((wm * 32 + mt * 16 + g) * 144 + tig * 4);
    uint32_t b_off[4];
#pragma unroll
    for (int nt = 0; nt < 4; nt++)
        b_off[nt] = (uint32_t)((wn * 32 + nt * 8 + g) * 144 + tig * 4);

    float4 xa[2];
    uint4  wb[8];
#pragma unroll
    for (int i = 0; i < 2; i++) xa[i] = *(const float4*)xp[i];
#pragma unroll
    for (int i = 0; i < 8; i++) wb[i] = *(const uint4*)wp[i];

    float accm[2][4][4];   // main-term fp32 RN accumulator
    float accc[2][4][4];   // correction-term MMA-chained accumulator
#pragma unroll
    for (int mt = 0; mt < 2; mt++)
#pragma unroll
        for (int nt = 0; nt < 4; nt++)
#pragma unroll
            for (int e = 0; e < 4; e++) {
                accm[mt][nt][e] = 0.0f;
                accc[mt][nt][e] = 0.0f;
            }

    // ---- prologue: store chunk 0 into stage 0 ----
    {
#pragma unroll
        for (int i = 0; i < 2; i++) {
            uint4 u0, u1;
            split2(xa[i].x, u0.x, u1.x);
            split2(xa[i].y, u0.y, u1.y);
            split2(xa[i].z, u0.z, u1.z);
            split2(xa[i].w, u0.w, u1.w);
            char* ba = sm + SM_AS0 + sxa_off[i];
            *(uint4*)(ba)        = u0;
            *(uint4*)(ba + ASPL) = u1;
        }
#pragma unroll
        for (int i = 0; i < 8; i++)
            *(uint4*)(sm + SM_BS0 + swb_off[i]) = wb[i];
    }
    __syncthreads();

    // ---- mainloop: 32 K-chunks of 32, double-buffered ----
    for (int ch = 0; ch < 32; ch++) {
        const int st = ch & 1;
        const char* a_stage = sm + SM_AS0 + st * AST;
        const char* b_stage = sm + SM_BS0 + st * BST;

        if (ch < 31) {
#pragma unroll
            for (int i = 0; i < 2; i++)
                xa[i] = *(const float4*)(xp[i] + (ch + 1) * 32);
#pragma unroll
            for (int i = 0; i < 8; i++)
                wb[i] = *(const uint4*)(wp[i] + (ch + 1) * 32);
        }

        // per-chunk zero-C accumulator for the main term
        float dm[2][4][4];
#pragma unroll
        for (int mt = 0; mt < 2; mt++)
#pragma unroll
            for (int nt = 0; nt < 4; nt++)
#pragma unroll
                for (int e = 0; e < 4; e++) dm[mt][nt][e] = 0.0f;

#pragma unroll
        for (int ks = 0; ks < 4; ks++) {
            const uint32_t kso = (uint32_t)ks * 32;   // 8 cols * 4B
            // B fragments: [split][nt][2]
            uint32_t bf[2][4][2];
#pragma unroll
            for (int s = 0; s < 2; s++)
#pragma unroll
                for (int nt = 0; nt < 4; nt++) {
                    const char* bb = b_stage + s * BSPL + b_off[nt] + kso;
                    bf[s][nt][0] = *(const uint32_t*)(bb);
                    bf[s][nt][1] = *(const uint32_t*)(bb + 16);
                }
            // A fragments: [split][mt][4]
            uint32_t af[2][2][4];
#pragma unroll
            for (int s = 0; s < 2; s++)
#pragma unroll
                for (int mt = 0; mt < 2; mt++) {
                    const char* ab = a_stage + s * ASPL + a_off[mt] + kso;
                    af[s][mt][0] = *(const uint32_t*)(ab);
                    af[s][mt][1] = *(const uint32_t*)(ab + 1152);  // row +8
                    af[s][mt][2] = *(const uint32_t*)(ab + 16);    // col +4
                    af[s][mt][3] = *(const uint32_t*)(ab + 1168);
                }
#pragma unroll
            for (int mt = 0; mt < 2; mt++)
#pragma unroll
                for (int nt = 0; nt < 4; nt++) {
                    mma_tf32(dm[mt][nt],   af[0][mt], bf[0][nt]);  // T0
                    mma_tf32(accc[mt][nt], af[0][mt], bf[1][nt]);  // A0*B1
                    mma_tf32(accc[mt][nt], af[1][mt], bf[0][nt]);  // A1*B0
                }
        }
        // drain main-term chunk sums with RN fp32 adds
#pragma unroll
        for (int mt = 0; mt < 2; mt++)
#pragma unroll
            for (int nt = 0; nt < 4; nt++)
#pragma unroll
                for (int e = 0; e < 4; e++)
                    accm[mt][nt][e] += dm[mt][nt][e];

        if (ch < 31) {
            const int nst = st ^ 1;
            char* astage = sm + SM_AS0 + nst * AST;
            char* bstage = sm + SM_BS0 + nst * BST;
#pragma unroll
            for (int i = 0; i < 2; i++) {
                uint4 u0, u1;
                split2(xa[i].x, u0.x, u1.x);
                split2(xa[i].y, u0.y, u1.y);
                split2(xa[i].z, u0.z, u1.z);
                split2(xa[i].w, u0.w, u1.w);
                char* ba = astage + sxa_off[i];
                *(uint4*)(ba)        = u0;
                *(uint4*)(ba + ASPL) = u1;
            }
#pragma unroll
            for (int i = 0; i < 8; i++)
                *(uint4*)(bstage + swb_off[i]) = wb[i];
        }
        __syncthreads();
    }

    // ---- epilogue 1: h = relu(C1 + b1) -> tf32 split into A2 tiles ----
#pragma unroll
    for (int mt = 0; mt < 2; mt++) {
        int r0 = wm * 32 + mt * 16 + g;
#pragma unroll
        for (int nt = 0; nt < 4; nt++) {
            int c0i = wn * 32 + nt * 8 + tig * 2;
            float h00 = fmaxf(accm[mt][nt][0] + accc[mt][nt][0] + b1s[c0i], 0.0f);
            float h01 = fmaxf(accm[mt][nt][1] + accc[mt][nt][1] + b1s[c0i + 1], 0.0f);
            float h10 = fmaxf(accm[mt][nt][2] + accc[mt][nt][2] + b1s[c0i], 0.0f);
            float h11 = fmaxf(accm[mt][nt][3] + accc[mt][nt][3] + b1s[c0i + 1], 0.0f);
            uint2 p0, p1;
            split2(h00, p0.x, p1.x);
            split2(h01, p0.y, p1.y);
            char* ba = sm + SM_A2 + r0 * 528 + c0i * 4;
            *(uint2*)(ba + 0 * A2SPL) = p0;
            *(uint2*)(ba + 1 * A2SPL) = p1;
            split2(h10, p0.x, p1.x);
            split2(h11, p0.y, p1.y);
            char* bb = sm + SM_A2 + (r0 + 8) * 528 + c0i * 4;
            *(uint2*)(bb + 0 * A2SPL) = p0;
            *(uint2*)(bb + 1 * A2SPL) = p1;
        }
    }
    __syncthreads();

    // ---- GEMM2: q = h @ W2^T (warp tile m32 x n8, K=128, 16 k8-steps) ----
    float accm2[2][4];
    float accc2[2][4];
#pragma unroll
    for (int mt = 0; mt < 2; mt++)
#pragma unroll
        for (int e = 0; e < 4; e++) {
            accm2[mt][e] = 0.0f;
            accc2[mt][e] = 0.0f;
        }

    uint32_t a2_off[2];
#pragma unroll
    for (int mt = 0; mt < 2; mt++)
        a2_off[mt] = (uint32_t)((wm * 32 + mt * 16 + g) * 528 + tig * 4);
    const uint32_t w2_off = (uint32_t)((wn * 8 + g) * 528 + tig * 4);

#pragma unroll
    for (int ks = 0; ks < 16; ks++) {
        const uint32_t kso = (uint32_t)ks * 32;
        uint32_t bf[2][2];
#pragma unroll
        for (int s = 0; s < 2; s++) {
            const char* bb = sm + SM_W2 + s * W2SPL + w2_off + kso;
            bf[s][0] = *(const uint32_t*)(bb);
            bf[s][1] = *(const uint32_t*)(bb + 16);
        }
        float d2[2][4];
#pragma unroll
        for (int mt = 0; mt < 2; mt++)
#pragma unroll
            for (int e = 0; e < 4; e++) d2[mt][e] = 0.0f;

#pragma unroll
        for (int mt = 0; mt < 2; mt++) {
            uint32_t af0[4], af1[4];
            const char* ab0 = sm + SM_A2 + 0 * A2SPL + a2_off[mt] + kso;
            const char* ab1 = sm + SM_A2 + 1 * A2SPL + a2_off[mt] + kso;
            af0[0] = *(const uint32_t*)(ab0);
            af0[1] = *(const uint32_t*)(ab0 + 4224);   // row +8 (stride 528)
            af0[2] = *(const uint32_t*)(ab0 + 16);
            af0[3] = *(const uint32_t*)(ab0 + 4240);
            af1[0] = *(const uint32_t*)(ab1);
            af1[1] = *(const uint32_t*)(ab1 + 4224);
            af1[2] = *(const uint32_t*)(ab1 + 16);
            af1[3] = *(const uint32_t*)(ab1 + 4240);
            mma_tf32(d2[mt],    af0, bf[0]);   // T0
            mma_tf32(accc2[mt], af0, bf[1]);   // A0*B1
            mma_tf32(accc2[mt], af1, bf[0]);   // A1*B0
        }
#pragma unroll
        for (int mt = 0; mt < 2; mt++)
#pragma unroll
            for (int e = 0; e < 4; e++) accm2[mt][e] += d2[mt][e];
    }

    // ---- epilogue 2: q + b2 -> global ----
#pragma unroll
    for (int mt = 0; mt < 2; mt++) {
        int r0  = t0b + wm * 32 + mt * 16 + g;
        int c0i = wn * 8 + tig * 2;
        float2 v0 = make_float2(accm2[mt][0] + accc2[mt][0] + b2s[c0i],
                                accm2[mt][1] + accc2[mt][1] + b2s[c0i + 1]);
        float2 v1 = make_float2(accm2[mt][2] + accc2[mt][2] + b2s[c0i],
                                accm2[mt][3] + accc2[mt][3] + b2s[c0i + 1]);
        *(float2*)&g_q[(size_t)r0 * 32 + c0i]       = v0;
        *(float2*)&g_q[(size_t)(r0 + 8) * 32 + c0i] = v1;
    }
}

// ===========================================================================
// Selection + gather kernel (proven logic, unchanged)
// ===========================================================================
__device__ __forceinline__ unsigned fmap(float f) {
    unsigned u = __float_as_uint(f);
    return (u & 0x80000000u) ? ~u : (u | 0x80000000u);
}
__device__ __forceinline__ float funmap(unsigned m) {
    return (m & 0x80000000u) ? __uint_as_float(m & 0x7FFFFFFFu)
                             : __uint_as_float(~m);
}

__device__ __forceinline__ void topk8_256(float sv[8], int lane,
                                          float* top_s, int* top_i) {
    for (int k = 0; k < KNN; k++) {
        float best = sv[0];
        int bj = 0;
#pragma unroll
        for (int j = 1; j < 8; j++) {
            if (sv[j] > best) { best = sv[j]; bj = j; }
        }
        unsigned u = fmap(best);
        unsigned g = __reduce_max_sync(0xFFFFFFFFu, u);
        unsigned cand = (u == g) ? (unsigned)(lane + 32 * bj) : 0xFFFFFFFFu;
        unsigned nw = __reduce_min_sync(0xFFFFFFFFu, cand);
        if (lane == (int)(nw & 31u)) {
            int jw = (int)(nw >> 5);
#pragma unroll
            for (int j = 0; j < 8; j++) {
                if (j == jw) sv[j] = -FLT_MAX;
            }
        }
        if (lane == 0) { top_s[k] = funmap(g); top_i[k] = (int)nw; }
    }
}

#define TPB2 16   // tokens per block

__global__ __launch_bounds__(256, 4)
void select_gather_kernel(const float* __restrict__ keys,
                          const float* __restrict__ values,
                          float* __restrict__ out)
{
    __shared__ float keysb[1024 * 9];
    __shared__ float wss[TPB2 * 16];
    __shared__ int   idxs[TPB2 * 16];
    __shared__ float top_s[8 * 2 * 8];
    __shared__ int   top_i[8 * 2 * 8];

    const int tid  = threadIdx.x;
    const int lane = tid & 31;
    const int warp = tid >> 5;
    const int t0   = blockIdx.x * TPB2;

    for (int e = tid; e < HEADS * 2 * N_KEYS * HALF_D; e += 256) {
        keysb[(e >> 3) * 9 + (e & 7)] = keys[e];
    }
    __syncthreads();

    // 32 tasks (16 tokens x 2 heads), 8 warps, 4 tasks each
    for (int it = 0; it < 4; it++) {
        const int task = it * 8 + warp;
        const int tl = task >> 1;
        const int h  = task & 1;
        const int t  = t0 + tl;

        float q1r[8], q2r[8];
        const float* qrow = &g_q[(size_t)t * 32 + h * 16];
#pragma unroll
        for (int c = 0; c < 8; c++) {
            q1r[c] = __ldg(qrow + c);
            q2r[c] = __ldg(qrow + 8 + c);
        }

        float s1v[8], s2v[8];
        const float* k1 = &keysb[(h * 2 + 0) * N_KEYS * 9];
        const float* k2 = &keysb[(h * 2 + 1) * N_KEYS * 9];
#pragma unroll
        for (int j = 0; j < 8; j++) {
            const int n = lane + 32 * j;
            const float* kr1 = k1 + n * 9;
            const float* kr2 = k2 + n * 9;
            float a1 = 0.0f, a2 = 0.0f;
#pragma unroll
            for (int c = 0; c < 8; c++) {
                a1 += q1r[c] * kr1[c];
                a2 += q2r[c] * kr2[c];
            }
            s1v[j] = a1;
            s2v[j] = a2;
        }

        float* ts1 = &top_s[(warp * 2 + 0) * 8];
        float* ts2 = &top_s[(warp * 2 + 1) * 8];
        int*   ti1 = &top_i[(warp * 2 + 0) * 8];
        int*   ti2 = &top_i[(warp * 2 + 1) * 8];
        topk8_256(s1v, lane, ts1, ti1);
        topk8_256(s2v, lane, ts2, ti2);
        __syncwarp();

        const int a  = lane >> 2;
        const int b0 = (2 * lane) & 7;
        float cv0 = ts1[a] + ts2[b0];
        float cv1 = ts1[a] + ts2[b0 + 1];

        float ek[KNN];
        int   iks[KNN];
        float v0 = 0.0f, esum = 0.0f;
#pragma unroll
        for (int k = 0; k < KNN; k++) {
            float best;
            int slot;
            if (cv1 > cv0) { best = cv1; slot = 1; }
            else           { best = cv0; slot = 0; }
            unsigned u = fmap(best);
            unsigned g = __reduce_max_sync(0xFFFFFFFFu, u);
            unsigned cand = (u == g) ? (unsigned)(2 * lane + slot) : 0xFFFFFFFFu;
            unsigned jw = __reduce_min_sync(0xFFFFFFFFu, cand);
            float val = funmap(g);
            if (k == 0) v0 = val;
            float e = expf(val - v0);
            esum += e;
            if (lane == (int)(jw >> 1)) {
                if (jw & 1u) cv1 = -FLT_MAX;
                else         cv0 = -FLT_MAX;
            }
            if (lane == 0) {
                int aa = (int)(jw >> 3);
                int bb = (int)(jw & 7u);
                ek[k]  = e;
                iks[k] = ti1[aa] * N_KEYS + ti2[bb];
            }
        }
        if (lane == 0) {
#pragma unroll
            for (int k = 0; k < KNN; k++) {
                wss[tl * 16 + h * 8 + k]  = ek[k] / esum;
                idxs[tl * 16 + h * 8 + k] = iks[k];
            }
        }
        __syncwarp();
    }
    __syncthreads();

    // gather: out[t] = sum_k w * values[idx]
    const size_t c4 = (size_t)tid * 4;   // 256 threads x float4 = 1024 cols
    for (int tl = 0; tl < TPB2; tl++) {
        float4 acc = make_float4(0.0f, 0.0f, 0.0f, 0.0f);
#pragma unroll
        for (int k = 0; k < 16; k++) {
            const float wk = wss[tl * 16 + k];
            const int row  = idxs[tl * 16 + k];
            const float4 v = *reinterpret_cast<const float4*>(
                &values[((size_t)row << 10) + c4]);
            acc.x += wk * v.x;
            acc.y += wk * v.y;
            acc.z += wk * v.z;
            acc.w += wk * v.w;
        }
        *reinterpret_cast<float4*>(&out[((size_t)(t0 + tl) << 10) + c4]) = acc;
    }
}

// ===========================================================================
// Launch
// ===========================================================================
extern "C" void kernel_launch(void* const* d_in, const int* in_sizes, int n_in,
                              void* d_out, int out_size) {
    const float* x      = (const float*)d_in[0];
    const float* W1     = (const float*)d_in[1];
    const float* b1     = (const float*)d_in[2];
    const float* W2     = (const float*)d_in[3];
    const float* b2     = (const float*)d_in[4];
    const float* keys   = (const float*)d_in[5];
    const float* values = (const float*)d_in[6];
    float* out = (float*)d_out;

    const int T = in_sizes[0] / D_IN;   // 8192

    cudaFuncSetAttribute(gemm_kernel,
                         cudaFuncAttributeMaxDynamicSharedMemorySize,
                         SMEM_GEMM_BYTES);

    split_w1_kernel<<<H_DIM * D_IN / 4 / 256, 256>>>(W1);
    gemm_kernel<<<T / 64, 256, SMEM_GEMM_BYTES>>>(x, b1, W2, b2);
    select_gather_kernel<<<T / TPB2, 256>>>(keys, values, out);
}